// round 15
// baseline (speedup 1.0000x reference)
#include <cuda_runtime.h>
#include <math.h>

#define B_    1024
#define S_    100
#define H_    128
#define SSZ_  100
#define G3_   384
#define NB_   8
#define NT_   256
#define SP_   104
#define STILE_ 20
#define FCK_  356
#define FCP_  360
#define NEARTOP_ 1e-5f

__device__ float  g_ih  [B_*S_*H_];
__device__ float  g_ip  [B_*S_*H_];
__device__ float  g_ipt [B_*S_*H_];
__device__ double g_ip64 [B_*S_*H_];
__device__ double g_ipt64[B_*S_*H_];

#define NEG_INF __int_as_float(0xff800000)

__device__ __forceinline__ float xla_tanh(float x){
    float xc = fminf(fmaxf(x, -7.90531110763549805f), 7.90531110763549805f);
    float x2 = __fmul_rn(xc, xc);
    float np = __fmaf_rn(x2, -2.76076847742355e-16f, 2.00018790482477e-13f);
    np = __fmaf_rn(x2, np, -8.60467152213735e-11f);
    np = __fmaf_rn(x2, np,  5.12229709037114e-08f);
    np = __fmaf_rn(x2, np,  1.48572235717979e-05f);
    np = __fmaf_rn(x2, np,  6.37261928875436e-04f);
    np = __fmaf_rn(x2, np,  4.89352455891786e-03f);
    np = __fmul_rn(np, xc);
    float dp = __fmaf_rn(x2,  1.19825839466702e-06f, 1.18534705686654e-04f);
    dp = __fmaf_rn(x2, dp,  2.26843463243900e-03f);
    dp = __fmaf_rn(x2, dp,  4.89352518554385e-03f);
    float r = __fdiv_rn(np, dp);
    return (fabsf(x) < 0.0004f) ? x : r;
}
__device__ __forceinline__ float xla_sig(float x){
    float t = xla_tanh(__fmul_rn(0.5f, x));
    return __fadd_rn(__fmul_rn(0.5f, t), 0.5f);
}
__device__ __forceinline__ float emb2(float x0, float x1, float w0, float w1, float b){
    return __fadd_rn(__fmaf_rn(x1, w1, __fmul_rn(x0, w0)), b);
}
__device__ __forceinline__ double tanh64p(double x){
    double xc = fmin(fmax(x, -7.90531110763549805), 7.90531110763549805);
    double x2 = xc*xc;
    double np = fma(x2, -2.76076847742355e-16, 2.00018790482477e-13);
    np = fma(x2, np, -8.60467152213735e-11);
    np = fma(x2, np,  5.12229709037114e-08);
    np = fma(x2, np,  1.48572235717979e-05);
    np = fma(x2, np,  6.37261928875436e-04);
    np = fma(x2, np,  4.89352455891786e-03);
    np = np*xc;
    double dp = fma(x2,  1.19825839466702e-06, 1.18534705686654e-04);
    dp = fma(x2, dp,  2.26843463243900e-03);
    dp = fma(x2, dp,  4.89352518554385e-03);
    double r = np/dp;
    return (fabs(x) < 0.0004) ? x : r;
}
__device__ __forceinline__ double sig64p(double x){ return fma(0.5, tanh64p(0.5*x), 0.5); }

// ---------------- K0 ----------------
__global__ void __launch_bounds__(256) precompute_kernel(
    const float* __restrict__ inst, const float* __restrict__ eiW,
    const float* __restrict__ eib,  const float* __restrict__ attnW,
    const float* __restrict__ ptrW)
{
    int b = blockIdx.x, s0 = blockIdx.y * STILE_;
    __shared__ float ih[STILE_][H_];
    int tid = threadIdx.x;
    for (int idx = tid; idx < STILE_*H_; idx += 256){
        int s = idx >> 7, h = idx & 127;
        const float* xp = inst + ((size_t)b*S_ + s0 + s)*2;
        float v = emb2(xp[0], xp[1], eiW[h*2], eiW[h*2+1], eib[h]);
        ih[s][h] = v;
        g_ih[((size_t)b*S_ + s0 + s)*H_ + h] = v;
    }
    __syncthreads();
    int h = tid & 127;
    const float* W = (tid < 128) ? attnW : ptrW;
    float* dst     = (tid < 128) ? g_ip  : g_ipt;
    float acc[STILE_];
    #pragma unroll
    for (int s=0;s<STILE_;s++) acc[s]=0.f;
    for (int k=0;k<H_;k++){
        float w = W[k*H_ + h];
        #pragma unroll
        for (int s=0;s<STILE_;s++) acc[s] = __fmaf_rn(ih[s][k], w, acc[s]);
    }
    #pragma unroll
    for (int s=0;s<STILE_;s++) dst[((size_t)b*S_ + s0 + s)*H_ + h] = acc[s];
}

// ---------------- K0b: f64 prefixes ----------------
__global__ void __launch_bounds__(256) precompute64_kernel(
    const float* __restrict__ attnW, const float* __restrict__ ptrW)
{
    int b = blockIdx.x, s0 = blockIdx.y * STILE_;
    int tid = threadIdx.x, h = tid & 127;
    const float* W = (tid < 128) ? attnW : ptrW;
    double* dst    = (tid < 128) ? g_ip64 : g_ipt64;
    const float* ih = g_ih + ((size_t)b*S_ + s0)*H_;
    double acc[STILE_];
    #pragma unroll
    for (int s=0;s<STILE_;s++) acc[s]=0.0;
    for (int k=0;k<H_;k++){
        double w = (double)W[k*H_ + h];
        #pragma unroll
        for (int s=0;s<STILE_;s++) acc[s] = fma((double)ih[s*H_+k], w, acc[s]);
    }
    #pragma unroll
    for (int s=0;s<STILE_;s++) dst[((size_t)b*S_ + s0 + s)*H_ + h] = acc[s];
}

// ---------------- f32 encoder helpers ----------------
template<int K>
__device__ __forceinline__ void gemv3_gates(
    const float* __restrict__ Wih, const float* __restrict__ Whh,
    const float* __restrict__ bih, const float* __restrict__ bhh,
    const float* sx, const float* sh, float* sgx, float* sgh, int tid)
{
    for (int j = tid; j < G3_; j += NT_){
        float ax[NB_], ah[NB_];
        #pragma unroll
        for (int b=0;b<NB_;b++){ ax[b]=0.f; ah[b]=0.f; }
        const float4* wx = (const float4*)(Wih + (size_t)j*K);
        #pragma unroll 4
        for (int kk=0; kk<K/4; kk++){
            float4 w = wx[kk];
            #pragma unroll
            for (int b=0;b<NB_;b++){
                float4 xv = *(const float4*)(sx + b*K + (kk<<2));
                ax[b]=__fmaf_rn(w.x,xv.x,ax[b]); ax[b]=__fmaf_rn(w.y,xv.y,ax[b]);
                ax[b]=__fmaf_rn(w.z,xv.z,ax[b]); ax[b]=__fmaf_rn(w.w,xv.w,ax[b]);
            }
        }
        const float4* wh = (const float4*)(Whh + (size_t)j*H_);
        #pragma unroll 4
        for (int kk=0; kk<H_/4; kk++){
            float4 w = wh[kk];
            #pragma unroll
            for (int b=0;b<NB_;b++){
                float4 hv = *(const float4*)(sh + b*H_ + (kk<<2));
                ah[b]=__fmaf_rn(w.x,hv.x,ah[b]); ah[b]=__fmaf_rn(w.y,hv.y,ah[b]);
                ah[b]=__fmaf_rn(w.z,hv.z,ah[b]); ah[b]=__fmaf_rn(w.w,hv.w,ah[b]);
            }
        }
        float bx = bih[j], bh = bhh[j];
        #pragma unroll
        for (int b=0;b<NB_;b++){
            sgx[b*G3_+j]=__fadd_rn(ax[b],bx);
            sgh[b*G3_+j]=__fadd_rn(ah[b],bh);
        }
    }
}
__device__ __forceinline__ void gru_update(const float* sgx, const float* sgh,
                                           float* sh, int tid)
{
    for (int idx=tid; idx<NB_*H_; idx+=NT_){
        int b = idx>>7, h = idx&127;
        float r = xla_sig(__fadd_rn(sgx[b*G3_+h],      sgh[b*G3_+h]));
        float z = xla_sig(__fadd_rn(sgx[b*G3_+H_+h],   sgh[b*G3_+H_+h]));
        float n = xla_tanh(__fadd_rn(sgx[b*G3_+2*H_+h], __fmul_rn(r, sgh[b*G3_+2*H_+h])));
        sh[idx] = __fadd_rn(__fmul_rn(__fsub_rn(1.0f, z), n), __fmul_rn(z, sh[idx]));
    }
}
__device__ __forceinline__ void proj_bcast(const float* __restrict__ Wbot,
                                           const float* sin_, float* sout, int tid)
{
    int h = tid & 127, grp = tid >> 7;
    float a0=0.f,a1=0.f,a2=0.f,a3=0.f;
    #pragma unroll 4
    for (int k=0;k<H_;k++){
        float w = Wbot[k*H_ + h];
        a0=__fmaf_rn(sin_[(grp*4+0)*H_+k],w,a0); a1=__fmaf_rn(sin_[(grp*4+1)*H_+k],w,a1);
        a2=__fmaf_rn(sin_[(grp*4+2)*H_+k],w,a2); a3=__fmaf_rn(sin_[(grp*4+3)*H_+k],w,a3);
    }
    sout[(grp*4+0)*H_+h]=a0; sout[(grp*4+1)*H_+h]=a1;
    sout[(grp*4+2)*H_+h]=a2; sout[(grp*4+3)*H_+h]=a3;
}
__device__ __forceinline__ float wsum(float v){
    #pragma unroll
    for (int off=16; off; off>>=1) v = __fadd_rn(v, __shfl_xor_sync(0xffffffffu, v, off));
    return v;
}
__device__ __forceinline__ float wmax(float v){
    #pragma unroll
    for (int off=16; off; off>>=1) v = fmaxf(v, __shfl_xor_sync(0xffffffffu, v, off));
    return v;
}
__device__ __forceinline__ void attn_scores_ctx(const float* shp,
    const float* __restrict__ vvec, float* ssc, float* sctx, int bb, int tid)
{
    int lane = tid & 31, b = tid >> 5;
    const float* ip = g_ip + (size_t)(bb+b)*S_*H_;
    float hp0 = shp[b*H_+lane],    hp1 = shp[b*H_+lane+32],
          hp2 = shp[b*H_+lane+64], hp3 = shp[b*H_+lane+96];
    float v0 = vvec[lane], v1 = vvec[lane+32], v2 = vvec[lane+64], v3 = vvec[lane+96];
    for (int s0=0; s0<S_; s0+=4){
        float acc[4];
        #pragma unroll
        for (int u=0;u<4;u++){
            const float* q = ip + (s0+u)*H_;
            float a = __fmul_rn(fmaxf(__fadd_rn(q[lane],    hp0), 0.f), v0);
            a = __fmaf_rn(fmaxf(__fadd_rn(q[lane+32], hp1), 0.f), v1, a);
            a = __fmaf_rn(fmaxf(__fadd_rn(q[lane+64], hp2), 0.f), v2, a);
            a = __fmaf_rn(fmaxf(__fadd_rn(q[lane+96], hp3), 0.f), v3, a);
            acc[u]=a;
        }
        #pragma unroll
        for (int off=16; off; off>>=1){
            #pragma unroll
            for (int u=0;u<4;u++)
                acc[u] = __fadd_rn(acc[u], __shfl_xor_sync(0xffffffffu, acc[u], off));
        }
        if (lane < 4) ssc[b*SP_ + s0 + lane] = acc[lane];
    }
    __syncwarp();
    float m = NEG_INF;
    for (int s=lane; s<S_; s+=32) m = fmaxf(m, ssc[b*SP_+s]);
    m = wmax(m);
    float sum = 0.f;
    for (int s=lane; s<S_; s+=32){
        float e = expf(__fsub_rn(ssc[b*SP_+s], m));
        ssc[b*SP_+s] = e;
        sum = __fadd_rn(sum, e);
    }
    sum = wsum(sum);
    __syncwarp();
    const float* ih = g_ih + (size_t)(bb+b)*S_*H_;
    float a0=0.f,a1=0.f,a2=0.f,a3=0.f;
    for (int s=0;s<S_;s++){
        float p = __fdiv_rn(ssc[b*SP_+s], sum);
        const float* q = ih + s*H_;
        a0=__fmaf_rn(p,q[lane],   a0); a1=__fmaf_rn(p,q[lane+32],a1);
        a2=__fmaf_rn(p,q[lane+64],a2); a3=__fmaf_rn(p,q[lane+96],a3);
    }
    sctx[b*H_+lane]=a0; sctx[b*H_+lane+32]=a1;
    sctx[b*H_+lane+64]=a2; sctx[b*H_+lane+96]=a3;
}

// ---------------- f64 decoder helpers ----------------
__device__ __forceinline__ void gemv64_384(const float* __restrict__ W, int K,
    const double* xd, double* outd, const float* __restrict__ bias, int tid)
{
    for (int j = tid; j < G3_; j += NT_){
        double acc[NB_];
        #pragma unroll
        for (int b=0;b<NB_;b++) acc[b]=0.0;
        const float* wr = W + (size_t)j*K;
        for (int k=0;k<K;k++){
            double w = (double)wr[k];
            #pragma unroll
            for (int b=0;b<NB_;b++) acc[b] = fma(w, xd[b*K+k], acc[b]);
        }
        double bj = (double)bias[j];
        #pragma unroll
        for (int b=0;b<NB_;b++) outd[b*G3_+j] = acc[b] + bj;
    }
}
__device__ __forceinline__ void gru64(const double* gx, const double* gh,
                                      double* hd, int tid)
{
    for (int idx=tid; idx<NB_*H_; idx+=NT_){
        int b = idx>>7, h = idx&127;
        double r = sig64p(gx[b*G3_+h]      + gh[b*G3_+h]);
        double z = sig64p(gx[b*G3_+H_+h]   + gh[b*G3_+H_+h]);
        double n = tanh64p(gx[b*G3_+2*H_+h] + r*gh[b*G3_+2*H_+h]);
        hd[idx] = (1.0 - z)*n + z*hd[idx];
    }
}
__device__ __forceinline__ void proj64(const float* __restrict__ Wbot,
                                       const double* xd, double* outd, int tid)
{
    int h = tid & 127, grp = tid >> 7;
    double a0=0,a1=0,a2=0,a3=0;
    for (int k=0;k<H_;k++){
        double w = (double)Wbot[k*H_+h];
        a0=fma(w,xd[(grp*4+0)*H_+k],a0); a1=fma(w,xd[(grp*4+1)*H_+k],a1);
        a2=fma(w,xd[(grp*4+2)*H_+k],a2); a3=fma(w,xd[(grp*4+3)*H_+k],a3);
    }
    outd[(grp*4+0)*H_+h]=a0; outd[(grp*4+1)*H_+h]=a1;
    outd[(grp*4+2)*H_+h]=a2; outd[(grp*4+3)*H_+h]=a3;
}
__device__ __forceinline__ double wsum64(double v){
    #pragma unroll
    for (int off=16; off; off>>=1) v += __shfl_xor_sync(0xffffffffu, v, off);
    return v;
}
__device__ __forceinline__ double wmax64(double v){
    #pragma unroll
    for (int off=16; off; off>>=1) v = fmax(v, __shfl_xor_sync(0xffffffffu, v, off));
    return v;
}
// decoder attention: f64 scores/softmax, probs QUANTIZED to f32 before context
__device__ __forceinline__ void attn64(const double* hpd,
    const float* __restrict__ vvec, double* sscd, double* ctxd, int bb, int tid)
{
    int lane = tid & 31, b = tid >> 5;
    const double* ip = g_ip64 + (size_t)(bb+b)*S_*H_;
    double hp0=hpd[b*H_+lane], hp1=hpd[b*H_+lane+32],
           hp2=hpd[b*H_+lane+64], hp3=hpd[b*H_+lane+96];
    double v0=(double)vvec[lane], v1=(double)vvec[lane+32],
           v2=(double)vvec[lane+64], v3=(double)vvec[lane+96];
    for (int s0=0; s0<S_; s0+=4){
        double acc[4];
        #pragma unroll
        for (int u=0;u<4;u++){
            const double* q = ip + (s0+u)*H_;
            double a = fmax(q[lane]+hp0,0.0)*v0;
            a = fma(fmax(q[lane+32]+hp1,0.0), v1, a);
            a = fma(fmax(q[lane+64]+hp2,0.0), v2, a);
            a = fma(fmax(q[lane+96]+hp3,0.0), v3, a);
            acc[u]=a;
        }
        #pragma unroll
        for (int off=16; off; off>>=1){
            #pragma unroll
            for (int u=0;u<4;u++)
                acc[u] += __shfl_xor_sync(0xffffffffu, acc[u], off);
        }
        if (lane < 4) sscd[b*SP_ + s0 + lane] = acc[lane];
    }
    __syncwarp();
    double m = -1e300;
    for (int s=lane; s<S_; s+=32) m = fmax(m, sscd[b*SP_+s]);
    m = wmax64(m);
    double sum = 0.0;
    for (int s=lane; s<S_; s+=32){
        double e = exp(sscd[b*SP_+s]-m);
        sscd[b*SP_+s] = e;
        sum += e;
    }
    sum = wsum64(sum);
    __syncwarp();
    const float* ih = g_ih + (size_t)(bb+b)*S_*H_;
    double a0=0,a1=0,a2=0,a3=0;
    for (int s=0;s<S_;s++){
        float p32 = (float)(sscd[b*SP_+s]/sum);   // ref's f32 prob estimate
        double p = (double)p32;
        const float* q = ih + s*H_;
        a0=fma(p,(double)q[lane],   a0); a1=fma(p,(double)q[lane+32],a1);
        a2=fma(p,(double)q[lane+64],a2); a3=fma(p,(double)q[lane+96],a3);
    }
    ctxd[b*H_+lane]=a0; ctxd[b*H_+lane+32]=a1;
    ctxd[b*H_+lane+64]=a2; ctxd[b*H_+lane+96]=a3;
}

// ---------------- K1 ----------------
__global__ void __launch_bounds__(NT_) vae_main(
    const float* __restrict__ inst,
    const int*   __restrict__ sol1, const int* __restrict__ sol2,
    const float* __restrict__ eps,
    const float* __restrict__ erW,  const float* __restrict__ erb,
    const float* __restrict__ attnW,const float* __restrict__ attnV,
    const float* __restrict__ gWih, const float* __restrict__ gWhh,
    const float* __restrict__ gbih, const float* __restrict__ gbhh,
    const float* __restrict__ dWih, const float* __restrict__ dWhh,
    const float* __restrict__ dbih, const float* __restrict__ dbhh,
    const float* __restrict__ e1W,  const float* __restrict__ e1b,
    const float* __restrict__ e2W,  const float* __restrict__ e2b,
    const float* __restrict__ ptrW, const float* __restrict__ ptrV,
    const float* __restrict__ p1W,  const float* __restrict__ p1b,
    const float* __restrict__ p2W,  const float* __restrict__ p2b,
    float* __restrict__ out)
{
    extern __shared__ double pool[];
    int tid = threadIdx.x;
    int bb  = blockIdx.x * NB_;

    float* out_mu = out;
    float* out_lv = out + (size_t)B_*SSZ_;
    float* out_z  = out + 2ull*B_*SSZ_;
    float* out_idx= out + 3ull*B_*SSZ_;
    float* out_lp = out + 3ull*B_*SSZ_ + (size_t)B_*S_;

    // ======== ENCODER (f32, unchanged bit path) ========
    {
        float* sm    = (float*)pool;
        float* sh1   = sm;
        float* sh2   = sh1 + NB_*H_;
        float* srh   = sh2 + NB_*H_;
        float* sctx  = srh + NB_*H_;
        float* shp   = sctx+ NB_*H_;
        float* sfcin = shp + NB_*H_;
        float* sgx   = sfcin + NB_*256;
        float* sgh   = sgx + NB_*G3_;
        float* ssc   = sgh + NB_*G3_;
        float* saux  = ssc + NB_*SP_;

        for (int i=tid;i<NB_*H_;i+=NT_){ sh1[i]=0.f; sh2[i]=0.f; }
        if (tid < NB_){
            int p = sol1[(size_t)(bb+tid)*S_];
            const float* xp = inst + ((size_t)(bb+tid)*S_+p)*2;
            saux[2*tid] = xp[0]; saux[2*tid+1] = xp[1];
        }
        __syncthreads();
        for (int i=tid;i<NB_*H_;i+=NT_){
            int b=i>>7, h=i&127;
            srh[i] = emb2(saux[2*b], saux[2*b+1], erW[2*h], erW[2*h+1], erb[h]);
        }
        __syncthreads();
        for (int t=1; t<S_; t++){
            gemv3_gates<H_>(gWih,gWhh,gbih,gbhh, srh, sh1, sgx, sgh, tid);
            __syncthreads();
            gru_update(sgx,sgh,sh1,tid);
            __syncthreads();
            proj_bcast(attnW + H_*H_, sh1, shp, tid);
            __syncthreads();
            attn_scores_ctx(shp, attnV, ssc, sctx, bb, tid);
            if (tid < NB_){
                int p = sol1[(size_t)(bb+tid)*S_ + t];
                const float* xp = inst + ((size_t)(bb+tid)*S_+p)*2;
                saux[2*tid] = xp[0]; saux[2*tid+1] = xp[1];
            }
            __syncthreads();
            for (int i=tid;i<NB_*H_;i+=NT_){
                int b=i>>7, h=i&127;
                float rv = emb2(saux[2*b], saux[2*b+1], erW[2*h], erW[2*h+1], erb[h]);
                srh[i] = rv;
                sfcin[b*256 + h]      = rv;
                sfcin[b*256 + H_ + h] = sctx[i];
            }
            __syncthreads();
            gemv3_gates<2*H_>(dWih,dWhh,dbih,dbhh, sfcin, sh2, sgx, sgh, tid);
            __syncthreads();
            gru_update(sgx,sgh,sh2,tid);
            __syncthreads();
        }
        for (int j=tid; j<SSZ_; j+=NT_){
            float am[NB_], al[NB_];
            #pragma unroll
            for (int b=0;b<NB_;b++){ am[b]=0.f; al[b]=0.f; }
            const float4* w1 = (const float4*)(e1W + (size_t)j*H_);
            const float4* w2 = (const float4*)(e2W + (size_t)j*H_);
            for (int kk=0;kk<H_/4;kk++){
                float4 a = w1[kk], c = w2[kk];
                #pragma unroll
                for (int b=0;b<NB_;b++){
                    float4 hv = *(const float4*)(sh2 + b*H_ + (kk<<2));
                    am[b]=__fmaf_rn(a.x,hv.x,am[b]); am[b]=__fmaf_rn(a.y,hv.y,am[b]);
                    am[b]=__fmaf_rn(a.z,hv.z,am[b]); am[b]=__fmaf_rn(a.w,hv.w,am[b]);
                    al[b]=__fmaf_rn(c.x,hv.x,al[b]); al[b]=__fmaf_rn(c.y,hv.y,al[b]);
                    al[b]=__fmaf_rn(c.z,hv.z,al[b]); al[b]=__fmaf_rn(c.w,hv.w,al[b]);
                }
            }
            #pragma unroll
            for (int b=0;b<NB_;b++){
                float mu=__fadd_rn(am[b], e1b[j]);
                float lv=__fadd_rn(al[b], e2b[j]);
                float ex = expf(__fmul_rn(0.5f, lv));
                float z  = __fadd_rn(mu, __fmul_rn(eps[(size_t)(bb+b)*SSZ_+j], ex));
                out_mu[(size_t)(bb+b)*SSZ_+j]=mu;
                out_lv[(size_t)(bb+b)*SSZ_+j]=lv;
                out_z [(size_t)(bb+b)*SSZ_+j]=z;
            }
        }
        __syncthreads();
    }

    // ======== DECODER (f64 state; f32-quantized prob decisions) ========
    double* d_h1  = pool;
    double* d_rh  = d_h1  + NB_*H_;
    double* d_hp  = d_rh  + NB_*H_;
    double* d_ctx = d_hp  + NB_*H_;
    double* d_fo  = d_ctx + NB_*H_;
    double* d_fcin= d_fo  + NB_*H_;
    double* d_f1  = d_fcin+ NB_*FCP_;
    double* d_gx  = d_f1  + NB_*256;
    double* d_gh  = d_gx  + NB_*G3_;
    double* d_ssc = d_gh  + NB_*G3_;
    float*  fbase = (float*)(d_ssc + NB_*SP_);
    float* sscf  = fbase;
    float* smask = sscf  + NB_*SP_;
    float* sZ    = smask + NB_*SP_;
    float* sfp   = sZ    + NB_*SSZ_;
    float* saux  = sfp   + NB_*H_;

    __syncthreads();
    for (int i=tid;i<NB_*SSZ_;i+=NT_){
        int b=i/SSZ_, j=i-b*SSZ_;
        sZ[i] = out_z[(size_t)(bb+b)*SSZ_+j];
    }
    for (int i=tid;i<NB_*H_;i+=NT_) d_h1[i]=0.0;
    for (int i=tid;i<NB_*S_;i+=NT_){ int b=i/S_, s=i-b*S_; smask[b*SP_+s]=1.f; }
    __syncthreads();
    if (tid < NB_){
        int p0 = sol2[(size_t)(bb+tid)*S_];
        smask[tid*SP_+p0] = 0.f;
        out_idx[(size_t)(bb+tid)*S_] = (float)p0;
    }
    __syncthreads();

    for (int t=1; t<S_; t++){
        if (tid < NB_){
            int p = sol2[(size_t)(bb+tid)*S_ + (t-1)];
            const float* xp = inst + ((size_t)(bb+tid)*S_+p)*2;
            saux[2*tid] = xp[0]; saux[2*tid+1] = xp[1];
        }
        __syncthreads();
        for (int i=tid;i<NB_*H_;i+=NT_){
            int b=i>>7, h=i&127;
            d_rh[i] = fma((double)saux[2*b+1], (double)erW[2*h+1],
                          (double)saux[2*b]*(double)erW[2*h]) + (double)erb[h];
        }
        __syncthreads();
        gemv64_384(gWih, H_, d_rh, d_gx, gbih, tid);
        gemv64_384(gWhh, H_, d_h1, d_gh, gbhh, tid);
        __syncthreads();
        gru64(d_gx, d_gh, d_h1, tid);
        __syncthreads();
        proj64(attnW + H_*H_, d_h1, d_hp, tid);
        __syncthreads();
        attn64(d_hp, attnV, d_ssc, d_ctx, bb, tid);
        __syncthreads();
        for (int i=tid;i<NB_*H_;i+=NT_){
            int b=i>>7, h=i&127;
            d_fcin[b*FCP_ + h]       = d_ctx[i];
            d_fcin[b*FCP_ + 228 + h] = d_rh[i];
        }
        for (int i=tid;i<NB_*SSZ_;i+=NT_){
            int b=i/SSZ_, j=i-b*SSZ_;
            d_fcin[b*FCP_ + H_ + j] = (double)sZ[i];
        }
        __syncthreads();
        {
            int j = tid;
            double acc[NB_];
            #pragma unroll
            for (int b=0;b<NB_;b++) acc[b]=0.0;
            const float* wr = p1W + (size_t)j*FCK_;
            for (int k=0;k<FCK_;k++){
                double w = (double)wr[k];
                #pragma unroll
                for (int b=0;b<NB_;b++) acc[b] = fma(w, d_fcin[b*FCP_+k], acc[b]);
            }
            double bj = (double)p1b[j];
            #pragma unroll
            for (int b=0;b<NB_;b++) d_f1[b*256+j] = acc[b] + bj;
        }
        __syncthreads();
        {
            int h = tid & 127, grp = tid >> 7;
            double a0=0,a1=0,a2=0,a3=0;
            const float* wr = p2W + (size_t)h*256;
            for (int k=0;k<256;k++){
                double w = (double)wr[k];
                a0=fma(w, d_f1[(grp*4+0)*256+k], a0);
                a1=fma(w, d_f1[(grp*4+1)*256+k], a1);
                a2=fma(w, d_f1[(grp*4+2)*256+k], a2);
                a3=fma(w, d_f1[(grp*4+3)*256+k], a3);
            }
            double bh = (double)p2b[h];
            d_fo[(grp*4+0)*H_+h]=a0+bh; d_fo[(grp*4+1)*H_+h]=a1+bh;
            d_fo[(grp*4+2)*H_+h]=a2+bh; d_fo[(grp*4+3)*H_+h]=a3+bh;
        }
        __syncthreads();
        proj64(ptrW + H_*H_, d_fo, d_hp, tid);
        __syncthreads();
        for (int i=tid;i<NB_*H_;i+=NT_) sfp[i] = (float)d_hp[i];
        __syncthreads();
        // ---- pointer select: f32 screen; f64 logits; argmax over f32-QUANTIZED probs ----
        {
            int lane = tid & 31, b = tid >> 5;
            const float* ipA = g_ipt + (size_t)(bb+b)*S_*H_;
            float fp0=sfp[b*H_+lane], fp1=sfp[b*H_+lane+32],
                  fp2=sfp[b*H_+lane+64], fp3=sfp[b*H_+lane+96];
            float v0=ptrV[lane], v1=ptrV[lane+32], v2=ptrV[lane+64], v3=ptrV[lane+96];
            for (int s0=0; s0<S_; s0+=4){
                float acc[4];
                #pragma unroll
                for (int u=0;u<4;u++){
                    const float* q = ipA + (s0+u)*H_;
                    float a = __fmul_rn(xla_tanh(__fadd_rn(q[lane],    fp0)), v0);
                    a = __fmaf_rn(xla_tanh(__fadd_rn(q[lane+32], fp1)), v1, a);
                    a = __fmaf_rn(xla_tanh(__fadd_rn(q[lane+64], fp2)), v2, a);
                    a = __fmaf_rn(xla_tanh(__fadd_rn(q[lane+96], fp3)), v3, a);
                    acc[u]=a;
                }
                #pragma unroll
                for (int off=16; off; off>>=1){
                    #pragma unroll
                    for (int u=0;u<4;u++)
                        acc[u] = __fadd_rn(acc[u], __shfl_xor_sync(0xffffffffu, acc[u], off));
                }
                if (lane < 4){
                    float msk = smask[b*SP_ + s0 + lane];
                    sscf[b*SP_ + s0 + lane] = (msk > 0.5f) ? acc[lane] : NEG_INF;
                }
            }
            __syncwarp();
            float m1 = NEG_INF;
            for (int s=lane; s<S_; s+=32) m1 = fmaxf(m1, sscf[b*SP_+s]);
            m1 = wmax(m1);
            float thr = m1 - NEARTOP_;
            const double* ipD = g_ipt64 + (size_t)(bb+b)*S_*H_;
            double hp0=d_hp[b*H_+lane], hp1=d_hp[b*H_+lane+32],
                   hp2=d_hp[b*H_+lane+64], hp3=d_hp[b*H_+lane+96];
            double dv0=(double)v0, dv1=(double)v1, dv2=(double)v2, dv3=(double)v3;
            for (int s=0; s<S_; s++){
                bool live = smask[b*SP_+s] > 0.5f;
                if (live && sscf[b*SP_+s] >= thr){
                    const double* q = ipD + s*H_;
                    double a = tanh64p(q[lane]+hp0)*dv0;
                    a = fma(tanh64p(q[lane+32]+hp1), dv1, a);
                    a = fma(tanh64p(q[lane+64]+hp2), dv2, a);
                    a = fma(tanh64p(q[lane+96]+hp3), dv3, a);
                    a = wsum64(a);
                    if (lane==0) d_ssc[b*SP_+s] = a;
                } else {
                    if (lane==0) d_ssc[b*SP_+s] = live ? (double)sscf[b*SP_+s] : -1e300;
                }
            }
            __syncwarp();
            double m = -1e300;
            for (int s=lane; s<S_; s+=32) m = fmax(m, d_ssc[b*SP_+s]);
            m = wmax64(m);
            double sum = 0.0;
            for (int s=lane; s<S_; s+=32) sum += exp(d_ssc[b*SP_+s]-m);
            sum = wsum64(sum);
            __syncwarp();
            // quantize probs to f32; argmax with FIRST-INDEX tie-break (ref's plateaus)
            float me = -1.0f; int mi = S_;
            for (int s=lane; s<S_; s+=32){
                float p32 = (float)(exp(d_ssc[b*SP_+s]-m)/sum);
                sscf[b*SP_+s] = p32;
                if (p32 > me){ me = p32; mi = s; }
            }
            #pragma unroll
            for (int off=16; off; off>>=1){
                float om = __shfl_xor_sync(0xffffffffu, me, off);
                int   oi = __shfl_xor_sync(0xffffffffu, mi, off);
                if (om > me || (om == me && oi < mi)){ me = om; mi = oi; }
            }
            __syncwarp();
            int tgt = sol2[(size_t)(bb+b)*S_ + t];
            if (lane == 0){
                out_lp[(size_t)(bb+b)*(S_-1) + (t-1)] = logf(sscf[b*SP_+tgt]);
                out_idx[(size_t)(bb+b)*S_ + t] = (float)mi;
                smask[b*SP_+tgt] = 0.f;
            }
        }
        __syncthreads();
    }
}

extern "C" void kernel_launch(void* const* d_in, const int* in_sizes, int n_in,
                              void* d_out, int out_size) {
    const float* inst = (const float*)d_in[0];
    const int*   sol1 = (const int*)  d_in[1];
    const int*   sol2 = (const int*)  d_in[2];
    const float* eps  = (const float*)d_in[3];
    const float* erW  = (const float*)d_in[6];
    const float* erb  = (const float*)d_in[7];
    const float* eiW  = (const float*)d_in[4];
    const float* eib  = (const float*)d_in[5];
    const float* attnW= (const float*)d_in[8];
    const float* attnV= (const float*)d_in[9];
    const float* gWih = (const float*)d_in[10];
    const float* gWhh = (const float*)d_in[11];
    const float* gbih = (const float*)d_in[12];
    const float* gbhh = (const float*)d_in[13];
    const float* dWih = (const float*)d_in[14];
    const float* dWhh = (const float*)d_in[15];
    const float* dbih = (const float*)d_in[16];
    const float* dbhh = (const float*)d_in[17];
    const float* e1W  = (const float*)d_in[18];
    const float* e1b  = (const float*)d_in[19];
    const float* e2W  = (const float*)d_in[20];
    const float* e2b  = (const float*)d_in[21];
    const float* ptrW = (const float*)d_in[22];
    const float* ptrV = (const float*)d_in[23];
    const float* p1W  = (const float*)d_in[24];
    const float* p1b  = (const float*)d_in[25];
    const float* p2W  = (const float*)d_in[26];
    const float* p2b  = (const float*)d_in[27];
    float* out = (float*)d_out;

    size_t dbl = (size_t)(5*NB_*H_ + NB_*FCP_ + NB_*256 + 2*NB_*G3_ + NB_*SP_);
    size_t flt = (size_t)(2*NB_*SP_ + NB_*SSZ_ + NB_*H_ + 2*NB_ + 32);
    size_t smem = dbl*sizeof(double) + flt*sizeof(float);
    cudaFuncSetAttribute(vae_main, cudaFuncAttributeMaxDynamicSharedMemorySize, (int)smem);

    dim3 gpre(B_, S_/STILE_);
    precompute_kernel<<<gpre, 256>>>(inst, eiW, eib, attnW, ptrW);
    precompute64_kernel<<<gpre, 256>>>(attnW, ptrW);
    vae_main<<<B_/NB_, NT_, smem>>>(inst, sol1, sol2, eps, erW, erb, attnW, attnV,
                                    gWih, gWhh, gbih, gbhh, dWih, dWhh, dbih, dbhh,
                                    e1W, e1b, e2W, e2b, ptrW, ptrV,
                                    p1W, p1b, p2W, p2b, out);
}

// round 16
// speedup vs baseline: 1.4943x; 1.4943x over previous
#include <cuda_runtime.h>
#include <math.h>

#define B_    1024
#define S_    100
#define H_    128
#define SSZ_  100
#define G3_   384
#define NB_   8
#define NT_   256
#define SP_   104
#define STILE_ 20
#define FCK_  356
#define NEARTOP_ 1e-5f

__device__ float g_ih  [B_*S_*H_];
__device__ float g_ip  [B_*S_*H_];
__device__ float g_ipt [B_*S_*H_];
__device__ float g_iph [B_*S_*H_];
__device__ float g_ipl [B_*S_*H_];
__device__ float g_ipth[B_*S_*H_];
__device__ float g_iptl[B_*S_*H_];

#define NEG_INF __int_as_float(0xff800000)

__device__ __forceinline__ float xla_tanh(float x){
    float xc = fminf(fmaxf(x, -7.90531110763549805f), 7.90531110763549805f);
    float x2 = __fmul_rn(xc, xc);
    float np = __fmaf_rn(x2, -2.76076847742355e-16f, 2.00018790482477e-13f);
    np = __fmaf_rn(x2, np, -8.60467152213735e-11f);
    np = __fmaf_rn(x2, np,  5.12229709037114e-08f);
    np = __fmaf_rn(x2, np,  1.48572235717979e-05f);
    np = __fmaf_rn(x2, np,  6.37261928875436e-04f);
    np = __fmaf_rn(x2, np,  4.89352455891786e-03f);
    np = __fmul_rn(np, xc);
    float dp = __fmaf_rn(x2,  1.19825839466702e-06f, 1.18534705686654e-04f);
    dp = __fmaf_rn(x2, dp,  2.26843463243900e-03f);
    dp = __fmaf_rn(x2, dp,  4.89352518554385e-03f);
    float r = __fdiv_rn(np, dp);
    return (fabsf(x) < 0.0004f) ? x : r;
}
__device__ __forceinline__ float xla_sig(float x){
    float t = xla_tanh(__fmul_rn(0.5f, x));
    return __fadd_rn(__fmul_rn(0.5f, t), 0.5f);
}
__device__ __forceinline__ float emb2(float x0, float x1, float w0, float w1, float b){
    return __fadd_rn(__fmaf_rn(x1, w1, __fmul_rn(x0, w0)), b);
}
__device__ __forceinline__ double tanh64p(double x){
    double xc = fmin(fmax(x, -7.90531110763549805), 7.90531110763549805);
    double x2 = xc*xc;
    double np = fma(x2, -2.76076847742355e-16, 2.00018790482477e-13);
    np = fma(x2, np, -8.60467152213735e-11);
    np = fma(x2, np,  5.12229709037114e-08);
    np = fma(x2, np,  1.48572235717979e-05);
    np = fma(x2, np,  6.37261928875436e-04);
    np = fma(x2, np,  4.89352455891786e-03);
    np = np*xc;
    double dp = fma(x2,  1.19825839466702e-06, 1.18534705686654e-04);
    dp = fma(x2, dp,  2.26843463243900e-03);
    dp = fma(x2, dp,  4.89352518554385e-03);
    double r = np/dp;
    return (fabs(x) < 0.0004) ? x : r;
}
__device__ __forceinline__ double sig64p(double x){ return fma(0.5, tanh64p(0.5*x), 0.5); }

// ---- compensated f32 (Dot2) primitives ----
__device__ __forceinline__ void dot2(float w, float xh, float xl, float &s, float &c){
    float p  = __fmul_rn(w, xh);
    float ep = __fmaf_rn(w, xh, -p);
    float t  = __fadd_rn(s, p);
    float z  = __fsub_rn(t, s);
    float es = __fadd_rn(__fsub_rn(s, __fsub_rn(t, z)), __fsub_rn(p, z));
    s = t;
    c = __fmaf_rn(w, xl, __fadd_rn(c, __fadd_rn(ep, es)));
}
__device__ __forceinline__ void dot2z(float w, float xh, float &s, float &c){
    float p  = __fmul_rn(w, xh);
    float ep = __fmaf_rn(w, xh, -p);
    float t  = __fadd_rn(s, p);
    float z  = __fsub_rn(t, s);
    float es = __fadd_rn(__fsub_rn(s, __fsub_rn(t, z)), __fsub_rn(p, z));
    s = t;
    c = __fadd_rn(c, __fadd_rn(ep, es));
}
__device__ __forceinline__ void dsplit(double d, float &h, float &l){
    h = (float)d; l = (float)(d - (double)h);
}

// ---------------- K0: inst_h + f32 prefixes ----------------
__global__ void __launch_bounds__(256) precompute_kernel(
    const float* __restrict__ inst, const float* __restrict__ eiW,
    const float* __restrict__ eib,  const float* __restrict__ attnW,
    const float* __restrict__ ptrW)
{
    int b = blockIdx.x, s0 = blockIdx.y * STILE_;
    __shared__ float ih[STILE_][H_];
    int tid = threadIdx.x;
    for (int idx = tid; idx < STILE_*H_; idx += 256){
        int s = idx >> 7, h = idx & 127;
        const float* xp = inst + ((size_t)b*S_ + s0 + s)*2;
        float v = emb2(xp[0], xp[1], eiW[h*2], eiW[h*2+1], eib[h]);
        ih[s][h] = v;
        g_ih[((size_t)b*S_ + s0 + s)*H_ + h] = v;
    }
    __syncthreads();
    int h = tid & 127;
    const float* W = (tid < 128) ? attnW : ptrW;
    float* dst     = (tid < 128) ? g_ip  : g_ipt;
    float acc[STILE_];
    #pragma unroll
    for (int s=0;s<STILE_;s++) acc[s]=0.f;
    for (int k=0;k<H_;k++){
        float w = W[k*H_ + h];
        #pragma unroll
        for (int s=0;s<STILE_;s++) acc[s] = __fmaf_rn(ih[s][k], w, acc[s]);
    }
    #pragma unroll
    for (int s=0;s<STILE_;s++) dst[((size_t)b*S_ + s0 + s)*H_ + h] = acc[s];
}

// ---------------- K0b: f64 prefixes stored as (hi,lo) pairs ----------------
__global__ void __launch_bounds__(256) precompute_pair_kernel(
    const float* __restrict__ attnW, const float* __restrict__ ptrW)
{
    int b = blockIdx.x, s0 = blockIdx.y * STILE_;
    int tid = threadIdx.x, h = tid & 127;
    const float* W = (tid < 128) ? attnW : ptrW;
    float* dh = (tid < 128) ? g_iph : g_ipth;
    float* dl = (tid < 128) ? g_ipl : g_iptl;
    const float* ih = g_ih + ((size_t)b*S_ + s0)*H_;
    double acc[STILE_];
    #pragma unroll
    for (int s=0;s<STILE_;s++) acc[s]=0.0;
    for (int k=0;k<H_;k++){
        double w = (double)W[k*H_ + h];
        #pragma unroll
        for (int s=0;s<STILE_;s++) acc[s] = fma((double)ih[s*H_+k], w, acc[s]);
    }
    #pragma unroll
    for (int s=0;s<STILE_;s++){
        float hi, lo; dsplit(acc[s], hi, lo);
        dh[((size_t)b*S_ + s0 + s)*H_ + h] = hi;
        dl[((size_t)b*S_ + s0 + s)*H_ + h] = lo;
    }
}

// ---------------- f32 encoder helpers (unchanged bit path) ----------------
template<int K>
__device__ __forceinline__ void gemv3_gates(
    const float* __restrict__ Wih, const float* __restrict__ Whh,
    const float* __restrict__ bih, const float* __restrict__ bhh,
    const float* sx, const float* sh, float* sgx, float* sgh, int tid)
{
    for (int j = tid; j < G3_; j += NT_){
        float ax[NB_], ah[NB_];
        #pragma unroll
        for (int b=0;b<NB_;b++){ ax[b]=0.f; ah[b]=0.f; }
        const float4* wx = (const float4*)(Wih + (size_t)j*K);
        #pragma unroll 4
        for (int kk=0; kk<K/4; kk++){
            float4 w = wx[kk];
            #pragma unroll
            for (int b=0;b<NB_;b++){
                float4 xv = *(const float4*)(sx + b*K + (kk<<2));
                ax[b]=__fmaf_rn(w.x,xv.x,ax[b]); ax[b]=__fmaf_rn(w.y,xv.y,ax[b]);
                ax[b]=__fmaf_rn(w.z,xv.z,ax[b]); ax[b]=__fmaf_rn(w.w,xv.w,ax[b]);
            }
        }
        const float4* wh = (const float4*)(Whh + (size_t)j*H_);
        #pragma unroll 4
        for (int kk=0; kk<H_/4; kk++){
            float4 w = wh[kk];
            #pragma unroll
            for (int b=0;b<NB_;b++){
                float4 hv = *(const float4*)(sh + b*H_ + (kk<<2));
                ah[b]=__fmaf_rn(w.x,hv.x,ah[b]); ah[b]=__fmaf_rn(w.y,hv.y,ah[b]);
                ah[b]=__fmaf_rn(w.z,hv.z,ah[b]); ah[b]=__fmaf_rn(w.w,hv.w,ah[b]);
            }
        }
        float bx = bih[j], bh = bhh[j];
        #pragma unroll
        for (int b=0;b<NB_;b++){
            sgx[b*G3_+j]=__fadd_rn(ax[b],bx);
            sgh[b*G3_+j]=__fadd_rn(ah[b],bh);
        }
    }
}
__device__ __forceinline__ void gru_update(const float* sgx, const float* sgh,
                                           float* sh, int tid)
{
    for (int idx=tid; idx<NB_*H_; idx+=NT_){
        int b = idx>>7, h = idx&127;
        float r = xla_sig(__fadd_rn(sgx[b*G3_+h],      sgh[b*G3_+h]));
        float z = xla_sig(__fadd_rn(sgx[b*G3_+H_+h],   sgh[b*G3_+H_+h]));
        float n = xla_tanh(__fadd_rn(sgx[b*G3_+2*H_+h], __fmul_rn(r, sgh[b*G3_+2*H_+h])));
        sh[idx] = __fadd_rn(__fmul_rn(__fsub_rn(1.0f, z), n), __fmul_rn(z, sh[idx]));
    }
}
__device__ __forceinline__ void proj_bcast(const float* __restrict__ Wbot,
                                           const float* sin_, float* sout, int tid)
{
    int h = tid & 127, grp = tid >> 7;
    float a0=0.f,a1=0.f,a2=0.f,a3=0.f;
    #pragma unroll 4
    for (int k=0;k<H_;k++){
        float w = Wbot[k*H_ + h];
        a0=__fmaf_rn(sin_[(grp*4+0)*H_+k],w,a0); a1=__fmaf_rn(sin_[(grp*4+1)*H_+k],w,a1);
        a2=__fmaf_rn(sin_[(grp*4+2)*H_+k],w,a2); a3=__fmaf_rn(sin_[(grp*4+3)*H_+k],w,a3);
    }
    sout[(grp*4+0)*H_+h]=a0; sout[(grp*4+1)*H_+h]=a1;
    sout[(grp*4+2)*H_+h]=a2; sout[(grp*4+3)*H_+h]=a3;
}
__device__ __forceinline__ float wsum(float v){
    #pragma unroll
    for (int off=16; off; off>>=1) v = __fadd_rn(v, __shfl_xor_sync(0xffffffffu, v, off));
    return v;
}
__device__ __forceinline__ float wmax(float v){
    #pragma unroll
    for (int off=16; off; off>>=1) v = fmaxf(v, __shfl_xor_sync(0xffffffffu, v, off));
    return v;
}
__device__ __forceinline__ double wsum64(double v){
    #pragma unroll
    for (int off=16; off; off>>=1) v += __shfl_xor_sync(0xffffffffu, v, off);
    return v;
}
__device__ __forceinline__ double wmax64(double v){
    #pragma unroll
    for (int off=16; off; off>>=1) v = fmax(v, __shfl_xor_sync(0xffffffffu, v, off));
    return v;
}
__device__ __forceinline__ void attn_scores_ctx(const float* shp,
    const float* __restrict__ vvec, float* ssc, float* sctx, int bb, int tid)
{
    int lane = tid & 31, b = tid >> 5;
    const float* ip = g_ip + (size_t)(bb+b)*S_*H_;
    float hp0 = shp[b*H_+lane],    hp1 = shp[b*H_+lane+32],
          hp2 = shp[b*H_+lane+64], hp3 = shp[b*H_+lane+96];
    float v0 = vvec[lane], v1 = vvec[lane+32], v2 = vvec[lane+64], v3 = vvec[lane+96];
    for (int s0=0; s0<S_; s0+=4){
        float acc[4];
        #pragma unroll
        for (int u=0;u<4;u++){
            const float* q = ip + (s0+u)*H_;
            float a = __fmul_rn(fmaxf(__fadd_rn(q[lane],    hp0), 0.f), v0);
            a = __fmaf_rn(fmaxf(__fadd_rn(q[lane+32], hp1), 0.f), v1, a);
            a = __fmaf_rn(fmaxf(__fadd_rn(q[lane+64], hp2), 0.f), v2, a);
            a = __fmaf_rn(fmaxf(__fadd_rn(q[lane+96], hp3), 0.f), v3, a);
            acc[u]=a;
        }
        #pragma unroll
        for (int off=16; off; off>>=1){
            #pragma unroll
            for (int u=0;u<4;u++)
                acc[u] = __fadd_rn(acc[u], __shfl_xor_sync(0xffffffffu, acc[u], off));
        }
        if (lane < 4) ssc[b*SP_ + s0 + lane] = acc[lane];
    }
    __syncwarp();
    float m = NEG_INF;
    for (int s=lane; s<S_; s+=32) m = fmaxf(m, ssc[b*SP_+s]);
    m = wmax(m);
    float sum = 0.f;
    for (int s=lane; s<S_; s+=32){
        float e = expf(__fsub_rn(ssc[b*SP_+s], m));
        ssc[b*SP_+s] = e;
        sum = __fadd_rn(sum, e);
    }
    sum = wsum(sum);
    __syncwarp();
    const float* ih = g_ih + (size_t)(bb+b)*S_*H_;
    float a0=0.f,a1=0.f,a2=0.f,a3=0.f;
    for (int s=0;s<S_;s++){
        float p = __fdiv_rn(ssc[b*SP_+s], sum);
        const float* q = ih + s*H_;
        a0=__fmaf_rn(p,q[lane],   a0); a1=__fmaf_rn(p,q[lane+32],a1);
        a2=__fmaf_rn(p,q[lane+64],a2); a3=__fmaf_rn(p,q[lane+96],a3);
    }
    sctx[b*H_+lane]=a0; sctx[b*H_+lane+32]=a1;
    sctx[b*H_+lane+64]=a2; sctx[b*H_+lane+96]=a3;
}

// ---------------- pair-state decoder helpers ----------------
// gates GEMV: 384 rows, K=128, (hi,lo) state input, pair output + bias(f64 add)
__device__ __forceinline__ void gemvp(const float* __restrict__ W,
    const float* xh, const float* xl, const float* __restrict__ bias,
    float* oh, float* ol, int tid)
{
    for (int j = tid; j < G3_; j += NT_){
        float s[NB_], c[NB_];
        #pragma unroll
        for (int b=0;b<NB_;b++){ s[b]=0.f; c[b]=0.f; }
        const float* wr = W + (size_t)j*H_;
        for (int k=0;k<H_;k++){
            float w = wr[k];
            #pragma unroll
            for (int b=0;b<NB_;b++) dot2(w, xh[b*H_+k], xl[b*H_+k], s[b], c[b]);
        }
        double bj = (double)bias[j];
        #pragma unroll
        for (int b=0;b<NB_;b++){
            double v = (double)s[b] + (double)c[b] + bj;
            dsplit(v, oh[b*G3_+j], ol[b*G3_+j]);
        }
    }
}
__device__ __forceinline__ void grup(const float* gxh, const float* gxl,
    const float* ghh_, const float* ghl_, float* hh, float* hl, int tid)
{
    for (int idx=tid; idx<NB_*H_; idx+=NT_){
        int b = idx>>7, h = idx&127;
        double gxr = (double)gxh[b*G3_+h]      + (double)gxl[b*G3_+h];
        double ghr = (double)ghh_[b*G3_+h]     + (double)ghl_[b*G3_+h];
        double gxz = (double)gxh[b*G3_+H_+h]   + (double)gxl[b*G3_+H_+h];
        double ghz = (double)ghh_[b*G3_+H_+h]  + (double)ghl_[b*G3_+H_+h];
        double gxn = (double)gxh[b*G3_+2*H_+h] + (double)gxl[b*G3_+2*H_+h];
        double ghn = (double)ghh_[b*G3_+2*H_+h]+ (double)ghl_[b*G3_+2*H_+h];
        double r = sig64p(gxr + ghr);
        double z = sig64p(gxz + ghz);
        double n = tanh64p(gxn + r*ghn);
        double hold = (double)hh[idx] + (double)hl[idx];
        dsplit((1.0 - z)*n + z*hold, hh[idx], hl[idx]);
    }
}
// H x H projection on pair state
__device__ __forceinline__ void projp(const float* __restrict__ Wbot,
    const float* xh, const float* xl, float* oh, float* ol, int tid)
{
    int h = tid & 127, grp = tid >> 7;
    float s[4], c[4];
    #pragma unroll
    for (int i=0;i<4;i++){ s[i]=0.f; c[i]=0.f; }
    for (int k=0;k<H_;k++){
        float w = Wbot[k*H_ + h];
        #pragma unroll
        for (int i=0;i<4;i++)
            dot2(w, xh[(grp*4+i)*H_+k], xl[(grp*4+i)*H_+k], s[i], c[i]);
    }
    #pragma unroll
    for (int i=0;i<4;i++)
        dsplit((double)s[i] + (double)c[i], oh[(grp*4+i)*H_+h], ol[(grp*4+i)*H_+h]);
}
// decoder attention: pair scores -> f64 softmax -> f32-quantized probs -> pair ctx
__device__ __forceinline__ void attnp(const float* hph, const float* hpl,
    const float* __restrict__ vvec, double* sscd,
    float* ctxh, float* ctxl, int bb, int tid)
{
    int lane = tid & 31, b = tid >> 5;
    const float* iph = g_iph + (size_t)(bb+b)*S_*H_;
    const float* ipl = g_ipl + (size_t)(bb+b)*S_*H_;
    for (int s=0; s<S_; s++){
        float sc=0.f, cc=0.f;
        #pragma unroll
        for (int j=0;j<4;j++){
            int h = lane + 32*j;
            float ph_=iph[s*H_+h], pl_=ipl[s*H_+h];
            float ah=hph[b*H_+h],  al=hpl[b*H_+h];
            float a = __fadd_rn(ph_, ah);
            float z = __fsub_rn(a, ph_);
            float e = __fadd_rn(__fsub_rn(ph_, __fsub_rn(a, z)), __fsub_rn(ah, z));
            float lo = __fadd_rn(__fadd_rn(pl_, al), e);
            if (a > 0.f) dot2(vvec[h], a, lo, sc, cc);
        }
        double d = (double)sc + (double)cc;
        d = wsum64(d);
        if (lane == 0) sscd[b*SP_+s] = d;
    }
    __syncwarp();
    double m = -1e300;
    for (int s=lane; s<S_; s+=32) m = fmax(m, sscd[b*SP_+s]);
    m = wmax64(m);
    double sum = 0.0;
    for (int s=lane; s<S_; s+=32){
        double e = exp(sscd[b*SP_+s]-m);
        sscd[b*SP_+s] = e;
        sum += e;
    }
    sum = wsum64(sum);
    __syncwarp();
    const float* ih = g_ih + (size_t)(bb+b)*S_*H_;
    float s0[4], c0[4];
    #pragma unroll
    for (int i=0;i<4;i++){ s0[i]=0.f; c0[i]=0.f; }
    for (int s=0;s<S_;s++){
        float p32 = (float)(sscd[b*SP_+s]/sum);
        #pragma unroll
        for (int i=0;i<4;i++)
            dot2z(p32, ih[s*H_+lane+32*i], s0[i], c0[i]);
    }
    #pragma unroll
    for (int i=0;i<4;i++)
        dsplit((double)s0[i]+(double)c0[i], ctxh[b*H_+lane+32*i], ctxl[b*H_+lane+32*i]);
}

// ---------------- K1 ----------------
__global__ void __launch_bounds__(NT_) vae_main(
    const float* __restrict__ inst,
    const int*   __restrict__ sol1, const int* __restrict__ sol2,
    const float* __restrict__ eps,
    const float* __restrict__ erW,  const float* __restrict__ erb,
    const float* __restrict__ attnW,const float* __restrict__ attnV,
    const float* __restrict__ gWih, const float* __restrict__ gWhh,
    const float* __restrict__ gbih, const float* __restrict__ gbhh,
    const float* __restrict__ dWih, const float* __restrict__ dWhh,
    const float* __restrict__ dbih, const float* __restrict__ dbhh,
    const float* __restrict__ e1W,  const float* __restrict__ e1b,
    const float* __restrict__ e2W,  const float* __restrict__ e2b,
    const float* __restrict__ ptrW, const float* __restrict__ ptrV,
    const float* __restrict__ p1W,  const float* __restrict__ p1b,
    const float* __restrict__ p2W,  const float* __restrict__ p2b,
    float* __restrict__ out)
{
    extern __shared__ double pool[];
    int tid = threadIdx.x;
    int bb  = blockIdx.x * NB_;

    float* out_mu = out;
    float* out_lv = out + (size_t)B_*SSZ_;
    float* out_z  = out + 2ull*B_*SSZ_;
    float* out_idx= out + 3ull*B_*SSZ_;
    float* out_lp = out + 3ull*B_*SSZ_ + (size_t)B_*S_;

    // ======== ENCODER (f32, unchanged bit path) ========
    {
        float* sm    = (float*)pool;
        float* sh1   = sm;
        float* sh2   = sh1 + NB_*H_;
        float* srh   = sh2 + NB_*H_;
        float* sctx  = srh + NB_*H_;
        float* shp   = sctx+ NB_*H_;
        float* sfcin = shp + NB_*H_;
        float* sgx   = sfcin + NB_*256;
        float* sgh   = sgx + NB_*G3_;
        float* ssc   = sgh + NB_*G3_;
        float* saux  = ssc + NB_*SP_;

        for (int i=tid;i<NB_*H_;i+=NT_){ sh1[i]=0.f; sh2[i]=0.f; }
        if (tid < NB_){
            int p = sol1[(size_t)(bb+tid)*S_];
            const float* xp = inst + ((size_t)(bb+tid)*S_+p)*2;
            saux[2*tid] = xp[0]; saux[2*tid+1] = xp[1];
        }
        __syncthreads();
        for (int i=tid;i<NB_*H_;i+=NT_){
            int b=i>>7, h=i&127;
            srh[i] = emb2(saux[2*b], saux[2*b+1], erW[2*h], erW[2*h+1], erb[h]);
        }
        __syncthreads();
        for (int t=1; t<S_; t++){
            gemv3_gates<H_>(gWih,gWhh,gbih,gbhh, srh, sh1, sgx, sgh, tid);
            __syncthreads();
            gru_update(sgx,sgh,sh1,tid);
            __syncthreads();
            proj_bcast(attnW + H_*H_, sh1, shp, tid);
            __syncthreads();
            attn_scores_ctx(shp, attnV, ssc, sctx, bb, tid);
            if (tid < NB_){
                int p = sol1[(size_t)(bb+tid)*S_ + t];
                const float* xp = inst + ((size_t)(bb+tid)*S_+p)*2;
                saux[2*tid] = xp[0]; saux[2*tid+1] = xp[1];
            }
            __syncthreads();
            for (int i=tid;i<NB_*H_;i+=NT_){
                int b=i>>7, h=i&127;
                float rv = emb2(saux[2*b], saux[2*b+1], erW[2*h], erW[2*h+1], erb[h]);
                srh[i] = rv;
                sfcin[b*256 + h]      = rv;
                sfcin[b*256 + H_ + h] = sctx[i];
            }
            __syncthreads();
            gemv3_gates<2*H_>(dWih,dWhh,dbih,dbhh, sfcin, sh2, sgx, sgh, tid);
            __syncthreads();
            gru_update(sgx,sgh,sh2,tid);
            __syncthreads();
        }
        for (int j=tid; j<SSZ_; j+=NT_){
            float am[NB_], al[NB_];
            #pragma unroll
            for (int b=0;b<NB_;b++){ am[b]=0.f; al[b]=0.f; }
            const float4* w1 = (const float4*)(e1W + (size_t)j*H_);
            const float4* w2 = (const float4*)(e2W + (size_t)j*H_);
            for (int kk=0;kk<H_/4;kk++){
                float4 a = w1[kk], c = w2[kk];
                #pragma unroll
                for (int b=0;b<NB_;b++){
                    float4 hv = *(const float4*)(sh2 + b*H_ + (kk<<2));
                    am[b]=__fmaf_rn(a.x,hv.x,am[b]); am[b]=__fmaf_rn(a.y,hv.y,am[b]);
                    am[b]=__fmaf_rn(a.z,hv.z,am[b]); am[b]=__fmaf_rn(a.w,hv.w,am[b]);
                    al[b]=__fmaf_rn(c.x,hv.x,al[b]); al[b]=__fmaf_rn(c.y,hv.y,al[b]);
                    al[b]=__fmaf_rn(c.z,hv.z,al[b]); al[b]=__fmaf_rn(c.w,hv.w,al[b]);
                }
            }
            #pragma unroll
            for (int b=0;b<NB_;b++){
                float mu=__fadd_rn(am[b], e1b[j]);
                float lv=__fadd_rn(al[b], e2b[j]);
                float ex = expf(__fmul_rn(0.5f, lv));
                float z  = __fadd_rn(mu, __fmul_rn(eps[(size_t)(bb+b)*SSZ_+j], ex));
                out_mu[(size_t)(bb+b)*SSZ_+j]=mu;
                out_lv[(size_t)(bb+b)*SSZ_+j]=lv;
                out_z [(size_t)(bb+b)*SSZ_+j]=z;
            }
        }
        __syncthreads();
    }

    // ======== DECODER (pair state; f32-quantized prob decisions) ========
    double* d_ssc = pool;                         // NB*SP doubles
    float* fb   = (float*)(d_ssc + NB_*SP_);
    float* h1h  = fb;            float* h1l  = h1h  + NB_*H_;
    float* rhh  = h1l  + NB_*H_; float* rhl  = rhh  + NB_*H_;
    float* hph  = rhl  + NB_*H_; float* hpl  = hph  + NB_*H_;
    float* ctxh = hpl  + NB_*H_; float* ctxl = ctxh + NB_*H_;
    float* foh  = ctxl + NB_*H_; float* fol  = foh  + NB_*H_;
    float* f1h  = fol  + NB_*H_; float* f1l  = f1h  + NB_*256;
    float* gxh  = f1l  + NB_*256;float* gxl  = gxh  + NB_*G3_;
    float* ghh  = gxl  + NB_*G3_;float* ghl  = ghh  + NB_*G3_;
    float* fzh  = ghl  + NB_*G3_;float* fzl  = fzh  + NB_*256;
    float* sscf = fzl  + NB_*256;
    float* smask= sscf + NB_*SP_;
    float* sZ   = smask+ NB_*SP_;
    float* saux = sZ   + NB_*SSZ_;

    __syncthreads();
    for (int i=tid;i<NB_*SSZ_;i+=NT_){
        int b=i/SSZ_, j=i-b*SSZ_;
        sZ[i] = out_z[(size_t)(bb+b)*SSZ_+j];
    }
    for (int i=tid;i<NB_*H_;i+=NT_){ h1h[i]=0.f; h1l[i]=0.f; }
    for (int i=tid;i<NB_*S_;i+=NT_){ int b=i/S_, s=i-b*S_; smask[b*SP_+s]=1.f; }
    __syncthreads();
    if (tid < NB_){
        int p0 = sol2[(size_t)(bb+tid)*S_];
        smask[tid*SP_+p0] = 0.f;
        out_idx[(size_t)(bb+tid)*S_] = (float)p0;
    }
    __syncthreads();
    // hoist fc1's Z slice: fz[j,b] = sum_k W1[j,128+k]*Z[b,k]
    {
        int j = tid;
        float s[NB_], c[NB_];
        #pragma unroll
        for (int b=0;b<NB_;b++){ s[b]=0.f; c[b]=0.f; }
        const float* wr = p1W + (size_t)j*FCK_ + H_;
        for (int k=0;k<SSZ_;k++){
            float w = wr[k];
            #pragma unroll
            for (int b=0;b<NB_;b++) dot2z(w, sZ[b*SSZ_+k], s[b], c[b]);
        }
        #pragma unroll
        for (int b=0;b<NB_;b++)
            dsplit((double)s[b]+(double)c[b], fzh[b*256+j], fzl[b*256+j]);
    }
    __syncthreads();

    for (int t=1; t<S_; t++){
        if (tid < NB_){
            int p = sol2[(size_t)(bb+tid)*S_ + (t-1)];
            const float* xp = inst + ((size_t)(bb+tid)*S_+p)*2;
            saux[2*tid] = xp[0]; saux[2*tid+1] = xp[1];
        }
        __syncthreads();
        for (int i=tid;i<NB_*H_;i+=NT_){
            int b=i>>7, h=i&127;
            double d = fma((double)saux[2*b+1], (double)erW[2*h+1],
                           (double)saux[2*b]*(double)erW[2*h]) + (double)erb[h];
            dsplit(d, rhh[i], rhl[i]);
        }
        __syncthreads();
        gemvp(gWih, rhh, rhl, gbih, gxh, gxl, tid);
        gemvp(gWhh, h1h, h1l, gbhh, ghh, ghl, tid);
        __syncthreads();
        grup(gxh, gxl, ghh, ghl, h1h, h1l, tid);
        __syncthreads();
        projp(attnW + H_*H_, h1h, h1l, hph, hpl, tid);
        __syncthreads();
        attnp(hph, hpl, attnV, d_ssc, ctxh, ctxl, bb, tid);
        __syncthreads();
        // fc1: ctx(128) + rh(128) chains + hoisted Z + bias
        {
            int j = tid;
            float s[NB_], c[NB_];
            #pragma unroll
            for (int b=0;b<NB_;b++){ s[b]=0.f; c[b]=0.f; }
            const float* wr = p1W + (size_t)j*FCK_;
            for (int k=0;k<H_;k++){
                float w = wr[k];
                #pragma unroll
                for (int b=0;b<NB_;b++) dot2(w, ctxh[b*H_+k], ctxl[b*H_+k], s[b], c[b]);
            }
            const float* wr2 = wr + 228;
            for (int k=0;k<H_;k++){
                float w = wr2[k];
                #pragma unroll
                for (int b=0;b<NB_;b++) dot2(w, rhh[b*H_+k], rhl[b*H_+k], s[b], c[b]);
            }
            double bj = (double)p1b[j];
            #pragma unroll
            for (int b=0;b<NB_;b++){
                double v = (double)s[b] + (double)c[b]
                         + (double)fzh[b*256+j] + (double)fzl[b*256+j] + bj;
                dsplit(v, f1h[b*256+j], f1l[b*256+j]);
            }
        }
        __syncthreads();
        // fc2
        {
            int h = tid & 127, grp = tid >> 7;
            float s[4], c[4];
            #pragma unroll
            for (int i=0;i<4;i++){ s[i]=0.f; c[i]=0.f; }
            const float* wr = p2W + (size_t)h*256;
            for (int k=0;k<256;k++){
                float w = wr[k];
                #pragma unroll
                for (int i=0;i<4;i++)
                    dot2(w, f1h[(grp*4+i)*256+k], f1l[(grp*4+i)*256+k], s[i], c[i]);
            }
            double bh = (double)p2b[h];
            #pragma unroll
            for (int i=0;i<4;i++)
                dsplit((double)s[i]+(double)c[i]+bh,
                       foh[(grp*4+i)*H_+h], fol[(grp*4+i)*H_+h]);
        }
        __syncthreads();
        projp(ptrW + H_*H_, foh, fol, hph, hpl, tid);
        __syncthreads();
        // ---- pointer select: f32 screen; f64 contender logits; f32-prob argmax ----
        {
            int lane = tid & 31, b = tid >> 5;
            const float* ipA = g_ipt + (size_t)(bb+b)*S_*H_;
            float fp0=hph[b*H_+lane], fp1=hph[b*H_+lane+32],
                  fp2=hph[b*H_+lane+64], fp3=hph[b*H_+lane+96];
            float v0=ptrV[lane], v1=ptrV[lane+32], v2=ptrV[lane+64], v3=ptrV[lane+96];
            for (int s0=0; s0<S_; s0+=4){
                float acc[4];
                #pragma unroll
                for (int u=0;u<4;u++){
                    const float* q = ipA + (s0+u)*H_;
                    float a = __fmul_rn(xla_tanh(__fadd_rn(q[lane],    fp0)), v0);
                    a = __fmaf_rn(xla_tanh(__fadd_rn(q[lane+32], fp1)), v1, a);
                    a = __fmaf_rn(xla_tanh(__fadd_rn(q[lane+64], fp2)), v2, a);
                    a = __fmaf_rn(xla_tanh(__fadd_rn(q[lane+96], fp3)), v3, a);
                    acc[u]=a;
                }
                #pragma unroll
                for (int off=16; off; off>>=1){
                    #pragma unroll
                    for (int u=0;u<4;u++)
                        acc[u] = __fadd_rn(acc[u], __shfl_xor_sync(0xffffffffu, acc[u], off));
                }
                if (lane < 4){
                    float msk = smask[b*SP_ + s0 + lane];
                    sscf[b*SP_ + s0 + lane] = (msk > 0.5f) ? acc[lane] : NEG_INF;
                }
            }
            __syncwarp();
            float m1 = NEG_INF;
            for (int s=lane; s<S_; s+=32) m1 = fmaxf(m1, sscf[b*SP_+s]);
            m1 = wmax(m1);
            float thr = m1 - NEARTOP_;
            const float* ipDh = g_ipth + (size_t)(bb+b)*S_*H_;
            const float* ipDl = g_iptl + (size_t)(bb+b)*S_*H_;
            double hp0=(double)hph[b*H_+lane]   +(double)hpl[b*H_+lane];
            double hq1=(double)hph[b*H_+lane+32]+(double)hpl[b*H_+lane+32];
            double hq2=(double)hph[b*H_+lane+64]+(double)hpl[b*H_+lane+64];
            double hq3=(double)hph[b*H_+lane+96]+(double)hpl[b*H_+lane+96];
            double dv0=(double)v0, dv1=(double)v1, dv2=(double)v2, dv3=(double)v3;
            for (int s=0; s<S_; s++){
                bool live = smask[b*SP_+s] > 0.5f;
                if (live && sscf[b*SP_+s] >= thr){
                    double q0=(double)ipDh[s*H_+lane]   +(double)ipDl[s*H_+lane];
                    double q1=(double)ipDh[s*H_+lane+32]+(double)ipDl[s*H_+lane+32];
                    double q2=(double)ipDh[s*H_+lane+64]+(double)ipDl[s*H_+lane+64];
                    double q3=(double)ipDh[s*H_+lane+96]+(double)ipDl[s*H_+lane+96];
                    double a = tanh64p(q0+hp0)*dv0;
                    a = fma(tanh64p(q1+hq1), dv1, a);
                    a = fma(tanh64p(q2+hq2), dv2, a);
                    a = fma(tanh64p(q3+hq3), dv3, a);
                    a = wsum64(a);
                    if (lane==0) d_ssc[b*SP_+s] = a;
                } else {
                    if (lane==0) d_ssc[b*SP_+s] = live ? (double)sscf[b*SP_+s] : -1e300;
                }
            }
            __syncwarp();
            double m = -1e300;
            for (int s=lane; s<S_; s+=32) m = fmax(m, d_ssc[b*SP_+s]);
            m = wmax64(m);
            double sum = 0.0;
            for (int s=lane; s<S_; s+=32) sum += exp(d_ssc[b*SP_+s]-m);
            sum = wsum64(sum);
            __syncwarp();
            float me = -1.0f; int mi = S_;
            for (int s=lane; s<S_; s+=32){
                float p32 = (float)(exp(d_ssc[b*SP_+s]-m)/sum);
                sscf[b*SP_+s] = p32;
                if (p32 > me){ me = p32; mi = s; }
            }
            #pragma unroll
            for (int off=16; off; off>>=1){
                float om = __shfl_xor_sync(0xffffffffu, me, off);
                int   oi = __shfl_xor_sync(0xffffffffu, mi, off);
                if (om > me || (om == me && oi < mi)){ me = om; mi = oi; }
            }
            __syncwarp();
            int tgt = sol2[(size_t)(bb+b)*S_ + t];
            if (lane == 0){
                out_lp[(size_t)(bb+b)*(S_-1) + (t-1)] = logf(sscf[b*SP_+tgt]);
                out_idx[(size_t)(bb+b)*S_ + t] = (float)mi;
                smask[b*SP_+tgt] = 0.f;
            }
        }
        __syncthreads();
    }
}

extern "C" void kernel_launch(void* const* d_in, const int* in_sizes, int n_in,
                              void* d_out, int out_size) {
    const float* inst = (const float*)d_in[0];
    const int*   sol1 = (const int*)  d_in[1];
    const int*   sol2 = (const int*)  d_in[2];
    const float* eps  = (const float*)d_in[3];
    const float* eiW  = (const float*)d_in[4];
    const float* eib  = (const float*)d_in[5];
    const float* erW  = (const float*)d_in[6];
    const float* erb  = (const float*)d_in[7];
    const float* attnW= (const float*)d_in[8];
    const float* attnV= (const float*)d_in[9];
    const float* gWih = (const float*)d_in[10];
    const float* gWhh = (const float*)d_in[11];
    const float* gbih = (const float*)d_in[12];
    const float* gbhh = (const float*)d_in[13];
    const float* dWih = (const float*)d_in[14];
    const float* dWhh = (const float*)d_in[15];
    const float* dbih = (const float*)d_in[16];
    const float* dbhh = (const float*)d_in[17];
    const float* e1W  = (const float*)d_in[18];
    const float* e1b  = (const float*)d_in[19];
    const float* e2W  = (const float*)d_in[20];
    const float* e2b  = (const float*)d_in[21];
    const float* ptrW = (const float*)d_in[22];
    const float* ptrV = (const float*)d_in[23];
    const float* p1W  = (const float*)d_in[24];
    const float* p1b  = (const float*)d_in[25];
    const float* p2W  = (const float*)d_in[26];
    const float* p2b  = (const float*)d_in[27];
    float* out = (float*)d_out;

    size_t dbl = (size_t)(NB_*SP_);
    size_t flt = (size_t)(10*NB_*H_ + 2*NB_*256 + 4*NB_*G3_ + 2*NB_*256
                        + 2*NB_*SP_ + NB_*SSZ_ + 2*NB_ + 64);
    size_t smem_dec = dbl*sizeof(double) + flt*sizeof(float);
    size_t smem_enc = (size_t)(5*NB_*H_ + NB_*256 + 2*NB_*G3_ + NB_*SP_ + 2*NB_ + 64)*sizeof(float);
    size_t smem = smem_dec > smem_enc ? smem_dec : smem_enc;
    cudaFuncSetAttribute(vae_main, cudaFuncAttributeMaxDynamicSharedMemorySize, (int)smem);

    dim3 gpre(B_, S_/STILE_);
    precompute_kernel<<<gpre, 256>>>(inst, eiW, eib, attnW, ptrW);
    precompute_pair_kernel<<<gpre, 256>>>(attnW, ptrW);
    vae_main<<<B_/NB_, NT_, smem>>>(inst, sol1, sol2, eps, erW, erb, attnW, attnV,
                                    gWih, gWhh, gbih, gbhh, dWih, dWhh, dbih, dbhh,
                                    e1W, e1b, e2W, e2b, ptrW, ptrV,
                                    p1W, p1b, p2W, p2b, out);
}

// round 17
// speedup vs baseline: 1.4969x; 1.0017x over previous
#include <cuda_runtime.h>
#include <math.h>

#define B_    1024
#define S_    100
#define H_    128
#define SSZ_  100
#define G3_   384
#define NB_   4
#define NT_   256
#define SP_   104
#define STILE_ 20
#define FCK_  356
#define NEARTOP_ 1e-5f

__device__ float g_ih  [B_*S_*H_];
__device__ float g_ip  [B_*S_*H_];
__device__ float g_ipt [B_*S_*H_];
__device__ float g_iph [B_*S_*H_];
__device__ float g_ipl [B_*S_*H_];
__device__ float g_ipth[B_*S_*H_];
__device__ float g_iptl[B_*S_*H_];

#define NEG_INF __int_as_float(0xff800000)

__device__ __forceinline__ float xla_tanh(float x){
    float xc = fminf(fmaxf(x, -7.90531110763549805f), 7.90531110763549805f);
    float x2 = __fmul_rn(xc, xc);
    float np = __fmaf_rn(x2, -2.76076847742355e-16f, 2.00018790482477e-13f);
    np = __fmaf_rn(x2, np, -8.60467152213735e-11f);
    np = __fmaf_rn(x2, np,  5.12229709037114e-08f);
    np = __fmaf_rn(x2, np,  1.48572235717979e-05f);
    np = __fmaf_rn(x2, np,  6.37261928875436e-04f);
    np = __fmaf_rn(x2, np,  4.89352455891786e-03f);
    np = __fmul_rn(np, xc);
    float dp = __fmaf_rn(x2,  1.19825839466702e-06f, 1.18534705686654e-04f);
    dp = __fmaf_rn(x2, dp,  2.26843463243900e-03f);
    dp = __fmaf_rn(x2, dp,  4.89352518554385e-03f);
    float r = __fdiv_rn(np, dp);
    return (fabsf(x) < 0.0004f) ? x : r;
}
__device__ __forceinline__ float xla_sig(float x){
    float t = xla_tanh(__fmul_rn(0.5f, x));
    return __fadd_rn(__fmul_rn(0.5f, t), 0.5f);
}
__device__ __forceinline__ float emb2(float x0, float x1, float w0, float w1, float b){
    return __fadd_rn(__fmaf_rn(x1, w1, __fmul_rn(x0, w0)), b);
}
__device__ __forceinline__ double tanh64p(double x){
    double xc = fmin(fmax(x, -7.90531110763549805), 7.90531110763549805);
    double x2 = xc*xc;
    double np = fma(x2, -2.76076847742355e-16, 2.00018790482477e-13);
    np = fma(x2, np, -8.60467152213735e-11);
    np = fma(x2, np,  5.12229709037114e-08);
    np = fma(x2, np,  1.48572235717979e-05);
    np = fma(x2, np,  6.37261928875436e-04);
    np = fma(x2, np,  4.89352455891786e-03);
    np = np*xc;
    double dp = fma(x2,  1.19825839466702e-06, 1.18534705686654e-04);
    dp = fma(x2, dp,  2.26843463243900e-03);
    dp = fma(x2, dp,  4.89352518554385e-03);
    double r = np/dp;
    return (fabs(x) < 0.0004) ? x : r;
}
__device__ __forceinline__ double sig64p(double x){ return fma(0.5, tanh64p(0.5*x), 0.5); }

__device__ __forceinline__ void dot2(float w, float xh, float xl, float &s, float &c){
    float p  = __fmul_rn(w, xh);
    float ep = __fmaf_rn(w, xh, -p);
    float t  = __fadd_rn(s, p);
    float z  = __fsub_rn(t, s);
    float es = __fadd_rn(__fsub_rn(s, __fsub_rn(t, z)), __fsub_rn(p, z));
    s = t;
    c = __fmaf_rn(w, xl, __fadd_rn(c, __fadd_rn(ep, es)));
}
__device__ __forceinline__ void dot2z(float w, float xh, float &s, float &c){
    float p  = __fmul_rn(w, xh);
    float ep = __fmaf_rn(w, xh, -p);
    float t  = __fadd_rn(s, p);
    float z  = __fsub_rn(t, s);
    float es = __fadd_rn(__fsub_rn(s, __fsub_rn(t, z)), __fsub_rn(p, z));
    s = t;
    c = __fadd_rn(c, __fadd_rn(ep, es));
}
__device__ __forceinline__ void dsplit(double d, float &h, float &l){
    h = (float)d; l = (float)(d - (double)h);
}

// ---------------- K0 ----------------
__global__ void __launch_bounds__(256) precompute_kernel(
    const float* __restrict__ inst, const float* __restrict__ eiW,
    const float* __restrict__ eib,  const float* __restrict__ attnW,
    const float* __restrict__ ptrW)
{
    int b = blockIdx.x, s0 = blockIdx.y * STILE_;
    __shared__ float ih[STILE_][H_];
    int tid = threadIdx.x;
    for (int idx = tid; idx < STILE_*H_; idx += 256){
        int s = idx >> 7, h = idx & 127;
        const float* xp = inst + ((size_t)b*S_ + s0 + s)*2;
        float v = emb2(xp[0], xp[1], eiW[h*2], eiW[h*2+1], eib[h]);
        ih[s][h] = v;
        g_ih[((size_t)b*S_ + s0 + s)*H_ + h] = v;
    }
    __syncthreads();
    int h = tid & 127;
    const float* W = (tid < 128) ? attnW : ptrW;
    float* dst     = (tid < 128) ? g_ip  : g_ipt;
    float acc[STILE_];
    #pragma unroll
    for (int s=0;s<STILE_;s++) acc[s]=0.f;
    for (int k=0;k<H_;k++){
        float w = W[k*H_ + h];
        #pragma unroll
        for (int s=0;s<STILE_;s++) acc[s] = __fmaf_rn(ih[s][k], w, acc[s]);
    }
    #pragma unroll
    for (int s=0;s<STILE_;s++) dst[((size_t)b*S_ + s0 + s)*H_ + h] = acc[s];
}

// ---------------- K0b ----------------
__global__ void __launch_bounds__(256) precompute_pair_kernel(
    const float* __restrict__ attnW, const float* __restrict__ ptrW)
{
    int b = blockIdx.x, s0 = blockIdx.y * STILE_;
    int tid = threadIdx.x, h = tid & 127;
    const float* W = (tid < 128) ? attnW : ptrW;
    float* dh = (tid < 128) ? g_iph : g_ipth;
    float* dl = (tid < 128) ? g_ipl : g_iptl;
    const float* ih = g_ih + ((size_t)b*S_ + s0)*H_;
    double acc[STILE_];
    #pragma unroll
    for (int s=0;s<STILE_;s++) acc[s]=0.0;
    for (int k=0;k<H_;k++){
        double w = (double)W[k*H_ + h];
        #pragma unroll
        for (int s=0;s<STILE_;s++) acc[s] = fma((double)ih[s*H_+k], w, acc[s]);
    }
    #pragma unroll
    for (int s=0;s<STILE_;s++){
        float hi, lo; dsplit(acc[s], hi, lo);
        dh[((size_t)b*S_ + s0 + s)*H_ + h] = hi;
        dl[((size_t)b*S_ + s0 + s)*H_ + h] = lo;
    }
}

// ---------------- f32 encoder helpers ----------------
template<int K>
__device__ __forceinline__ void gemv3_gates(
    const float* __restrict__ Wih, const float* __restrict__ Whh,
    const float* __restrict__ bih, const float* __restrict__ bhh,
    const float* sx, const float* sh, float* sgx, float* sgh, int tid)
{
    for (int j = tid; j < G3_; j += NT_){
        float ax[NB_], ah[NB_];
        #pragma unroll
        for (int b=0;b<NB_;b++){ ax[b]=0.f; ah[b]=0.f; }
        const float4* wx = (const float4*)(Wih + (size_t)j*K);
        #pragma unroll 4
        for (int kk=0; kk<K/4; kk++){
            float4 w = wx[kk];
            #pragma unroll
            for (int b=0;b<NB_;b++){
                float4 xv = *(const float4*)(sx + b*K + (kk<<2));
                ax[b]=__fmaf_rn(w.x,xv.x,ax[b]); ax[b]=__fmaf_rn(w.y,xv.y,ax[b]);
                ax[b]=__fmaf_rn(w.z,xv.z,ax[b]); ax[b]=__fmaf_rn(w.w,xv.w,ax[b]);
            }
        }
        const float4* wh = (const float4*)(Whh + (size_t)j*H_);
        #pragma unroll 4
        for (int kk=0; kk<H_/4; kk++){
            float4 w = wh[kk];
            #pragma unroll
            for (int b=0;b<NB_;b++){
                float4 hv = *(const float4*)(sh + b*H_ + (kk<<2));
                ah[b]=__fmaf_rn(w.x,hv.x,ah[b]); ah[b]=__fmaf_rn(w.y,hv.y,ah[b]);
                ah[b]=__fmaf_rn(w.z,hv.z,ah[b]); ah[b]=__fmaf_rn(w.w,hv.w,ah[b]);
            }
        }
        float bx = bih[j], bh = bhh[j];
        #pragma unroll
        for (int b=0;b<NB_;b++){
            sgx[b*G3_+j]=__fadd_rn(ax[b],bx);
            sgh[b*G3_+j]=__fadd_rn(ah[b],bh);
        }
    }
}
__device__ __forceinline__ void gru_update(const float* sgx, const float* sgh,
                                           float* sh, int tid)
{
    for (int idx=tid; idx<NB_*H_; idx+=NT_){
        int b = idx>>7, h = idx&127;
        float r = xla_sig(__fadd_rn(sgx[b*G3_+h],      sgh[b*G3_+h]));
        float z = xla_sig(__fadd_rn(sgx[b*G3_+H_+h],   sgh[b*G3_+H_+h]));
        float n = xla_tanh(__fadd_rn(sgx[b*G3_+2*H_+h], __fmul_rn(r, sgh[b*G3_+2*H_+h])));
        sh[idx] = __fadd_rn(__fmul_rn(__fsub_rn(1.0f, z), n), __fmul_rn(z, sh[idx]));
    }
}
// 2 batch elems per thread-group (NB=4, 256 threads)
__device__ __forceinline__ void proj_bcast(const float* __restrict__ Wbot,
                                           const float* sin_, float* sout, int tid)
{
    int h = tid & 127, gsel = tid >> 7;   // 0/1
    float a0=0.f,a1=0.f;
    #pragma unroll 4
    for (int k=0;k<H_;k++){
        float w = Wbot[k*H_ + h];
        a0=__fmaf_rn(sin_[(gsel*2+0)*H_+k],w,a0);
        a1=__fmaf_rn(sin_[(gsel*2+1)*H_+k],w,a1);
    }
    sout[(gsel*2+0)*H_+h]=a0; sout[(gsel*2+1)*H_+h]=a1;
}
__device__ __forceinline__ float wsum(float v){
    #pragma unroll
    for (int off=16; off; off>>=1) v = __fadd_rn(v, __shfl_xor_sync(0xffffffffu, v, off));
    return v;
}
__device__ __forceinline__ float wmax(float v){
    #pragma unroll
    for (int off=16; off; off>>=1) v = fmaxf(v, __shfl_xor_sync(0xffffffffu, v, off));
    return v;
}
__device__ __forceinline__ double wsum64(double v){
    #pragma unroll
    for (int off=16; off; off>>=1) v += __shfl_xor_sync(0xffffffffu, v, off);
    return v;
}
__device__ __forceinline__ double wmax64(double v){
    #pragma unroll
    for (int off=16; off; off>>=1) v = fmax(v, __shfl_xor_sync(0xffffffffu, v, off));
    return v;
}
__device__ __forceinline__ void attn_scores_ctx(const float* shp,
    const float* __restrict__ vvec, float* ssc, float* sctx, int bb, int tid)
{
    int lane = tid & 31, b = tid >> 5;
    if (b >= NB_) return;
    const float* ip = g_ip + (size_t)(bb+b)*S_*H_;
    float hp0 = shp[b*H_+lane],    hp1 = shp[b*H_+lane+32],
          hp2 = shp[b*H_+lane+64], hp3 = shp[b*H_+lane+96];
    float v0 = vvec[lane], v1 = vvec[lane+32], v2 = vvec[lane+64], v3 = vvec[lane+96];
    for (int s0=0; s0<S_; s0+=4){
        float acc[4];
        #pragma unroll
        for (int u=0;u<4;u++){
            const float* q = ip + (s0+u)*H_;
            float a = __fmul_rn(fmaxf(__fadd_rn(q[lane],    hp0), 0.f), v0);
            a = __fmaf_rn(fmaxf(__fadd_rn(q[lane+32], hp1), 0.f), v1, a);
            a = __fmaf_rn(fmaxf(__fadd_rn(q[lane+64], hp2), 0.f), v2, a);
            a = __fmaf_rn(fmaxf(__fadd_rn(q[lane+96], hp3), 0.f), v3, a);
            acc[u]=a;
        }
        #pragma unroll
        for (int off=16; off; off>>=1){
            #pragma unroll
            for (int u=0;u<4;u++)
                acc[u] = __fadd_rn(acc[u], __shfl_xor_sync(0xffffffffu, acc[u], off));
        }
        if (lane < 4) ssc[b*SP_ + s0 + lane] = acc[lane];
    }
    __syncwarp();
    float m = NEG_INF;
    for (int s=lane; s<S_; s+=32) m = fmaxf(m, ssc[b*SP_+s]);
    m = wmax(m);
    float sum = 0.f;
    for (int s=lane; s<S_; s+=32){
        float e = expf(__fsub_rn(ssc[b*SP_+s], m));
        ssc[b*SP_+s] = e;
        sum = __fadd_rn(sum, e);
    }
    sum = wsum(sum);
    __syncwarp();
    const float* ih = g_ih + (size_t)(bb+b)*S_*H_;
    float a0=0.f,a1=0.f,a2=0.f,a3=0.f;
    for (int s=0;s<S_;s++){
        float p = __fdiv_rn(ssc[b*SP_+s], sum);
        const float* q = ih + s*H_;
        a0=__fmaf_rn(p,q[lane],   a0); a1=__fmaf_rn(p,q[lane+32],a1);
        a2=__fmaf_rn(p,q[lane+64],a2); a3=__fmaf_rn(p,q[lane+96],a3);
    }
    sctx[b*H_+lane]=a0; sctx[b*H_+lane+32]=a1;
    sctx[b*H_+lane+64]=a2; sctx[b*H_+lane+96]=a3;
}

// ---------------- pair-state decoder helpers ----------------
__device__ __forceinline__ void gemvp(const float* __restrict__ W,
    const float* xh, const float* xl, const float* __restrict__ bias,
    float* oh, float* ol, int tid)
{
    for (int j = tid; j < G3_; j += NT_){
        float s[NB_], c[NB_];
        #pragma unroll
        for (int b=0;b<NB_;b++){ s[b]=0.f; c[b]=0.f; }
        const float* wr = W + (size_t)j*H_;
        for (int k=0;k<H_;k++){
            float w = wr[k];
            #pragma unroll
            for (int b=0;b<NB_;b++) dot2(w, xh[b*H_+k], xl[b*H_+k], s[b], c[b]);
        }
        double bj = (double)bias[j];
        #pragma unroll
        for (int b=0;b<NB_;b++){
            double v = (double)s[b] + (double)c[b] + bj;
            dsplit(v, oh[b*G3_+j], ol[b*G3_+j]);
        }
    }
}
__device__ __forceinline__ void grup(const float* gxh, const float* gxl,
    const float* ghh_, const float* ghl_, float* hh, float* hl, int tid)
{
    for (int idx=tid; idx<NB_*H_; idx+=NT_){
        int b = idx>>7, h = idx&127;
        double gxr = (double)gxh[b*G3_+h]      + (double)gxl[b*G3_+h];
        double ghr = (double)ghh_[b*G3_+h]     + (double)ghl_[b*G3_+h];
        double gxz = (double)gxh[b*G3_+H_+h]   + (double)gxl[b*G3_+H_+h];
        double ghz = (double)ghh_[b*G3_+H_+h]  + (double)ghl_[b*G3_+H_+h];
        double gxn = (double)gxh[b*G3_+2*H_+h] + (double)gxl[b*G3_+2*H_+h];
        double ghn = (double)ghh_[b*G3_+2*H_+h]+ (double)ghl_[b*G3_+2*H_+h];
        double r = sig64p(gxr + ghr);
        double z = sig64p(gxz + ghz);
        double n = tanh64p(gxn + r*ghn);
        double hold = (double)hh[idx] + (double)hl[idx];
        dsplit((1.0 - z)*n + z*hold, hh[idx], hl[idx]);
    }
}
__device__ __forceinline__ void projp(const float* __restrict__ Wbot,
    const float* xh, const float* xl, float* oh, float* ol, int tid)
{
    int h = tid & 127, gsel = tid >> 7;   // 0/1 -> b pairs
    float s[2], c[2];
    #pragma unroll
    for (int i=0;i<2;i++){ s[i]=0.f; c[i]=0.f; }
    for (int k=0;k<H_;k++){
        float w = Wbot[k*H_ + h];
        #pragma unroll
        for (int i=0;i<2;i++)
            dot2(w, xh[(gsel*2+i)*H_+k], xl[(gsel*2+i)*H_+k], s[i], c[i]);
    }
    #pragma unroll
    for (int i=0;i<2;i++)
        dsplit((double)s[i] + (double)c[i], oh[(gsel*2+i)*H_+h], ol[(gsel*2+i)*H_+h]);
}
__device__ __forceinline__ void attnp(const float* hph, const float* hpl,
    const float* __restrict__ vvec, double* sscd,
    float* ctxh, float* ctxl, int bb, int tid)
{
    int lane = tid & 31, b = tid >> 5;
    if (b >= NB_) return;
    const float* iph = g_iph + (size_t)(bb+b)*S_*H_;
    const float* ipl = g_ipl + (size_t)(bb+b)*S_*H_;
    for (int s=0; s<S_; s++){
        float sc=0.f, cc=0.f;
        #pragma unroll
        for (int j=0;j<4;j++){
            int h = lane + 32*j;
            float ph_=iph[s*H_+h], pl_=ipl[s*H_+h];
            float ah=hph[b*H_+h],  al=hpl[b*H_+h];
            float a = __fadd_rn(ph_, ah);
            float z = __fsub_rn(a, ph_);
            float e = __fadd_rn(__fsub_rn(ph_, __fsub_rn(a, z)), __fsub_rn(ah, z));
            float lo = __fadd_rn(__fadd_rn(pl_, al), e);
            if (a > 0.f) dot2(vvec[h], a, lo, sc, cc);
        }
        double d = (double)sc + (double)cc;
        d = wsum64(d);
        if (lane == 0) sscd[b*SP_+s] = d;
    }
    __syncwarp();
    double m = -1e300;
    for (int s=lane; s<S_; s+=32) m = fmax(m, sscd[b*SP_+s]);
    m = wmax64(m);
    double sum = 0.0;
    for (int s=lane; s<S_; s+=32){
        double e = exp(sscd[b*SP_+s]-m);
        sscd[b*SP_+s] = e;
        sum += e;
    }
    sum = wsum64(sum);
    __syncwarp();
    const float* ih = g_ih + (size_t)(bb+b)*S_*H_;
    float s0[4], c0[4];
    #pragma unroll
    for (int i=0;i<4;i++){ s0[i]=0.f; c0[i]=0.f; }
    for (int s=0;s<S_;s++){
        float p32 = (float)(sscd[b*SP_+s]/sum);
        #pragma unroll
        for (int i=0;i<4;i++)
            dot2z(p32, ih[s*H_+lane+32*i], s0[i], c0[i]);
    }
    #pragma unroll
    for (int i=0;i<4;i++)
        dsplit((double)s0[i]+(double)c0[i], ctxh[b*H_+lane+32*i], ctxl[b*H_+lane+32*i]);
}

// ---------------- K1 ----------------
__global__ void __launch_bounds__(NT_) vae_main(
    const float* __restrict__ inst,
    const int*   __restrict__ sol1, const int* __restrict__ sol2,
    const float* __restrict__ eps,
    const float* __restrict__ erW,  const float* __restrict__ erb,
    const float* __restrict__ attnW,const float* __restrict__ attnV,
    const float* __restrict__ gWih, const float* __restrict__ gWhh,
    const float* __restrict__ gbih, const float* __restrict__ gbhh,
    const float* __restrict__ dWih, const float* __restrict__ dWhh,
    const float* __restrict__ dbih, const float* __restrict__ dbhh,
    const float* __restrict__ e1W,  const float* __restrict__ e1b,
    const float* __restrict__ e2W,  const float* __restrict__ e2b,
    const float* __restrict__ ptrW, const float* __restrict__ ptrV,
    const float* __restrict__ p1W,  const float* __restrict__ p1b,
    const float* __restrict__ p2W,  const float* __restrict__ p2b,
    float* __restrict__ out)
{
    extern __shared__ double pool[];
    int tid = threadIdx.x;
    int bb  = blockIdx.x * NB_;

    float* out_mu = out;
    float* out_lv = out + (size_t)B_*SSZ_;
    float* out_z  = out + 2ull*B_*SSZ_;
    float* out_idx= out + 3ull*B_*SSZ_;
    float* out_lp = out + 3ull*B_*SSZ_ + (size_t)B_*S_;

    // ======== ENCODER (f32, bit path) ========
    {
        float* sm    = (float*)pool;
        float* sh1   = sm;
        float* sh2   = sh1 + NB_*H_;
        float* srh   = sh2 + NB_*H_;
        float* sctx  = srh + NB_*H_;
        float* shp   = sctx+ NB_*H_;
        float* sfcin = shp + NB_*H_;
        float* sgx   = sfcin + NB_*256;
        float* sgh   = sgx + NB_*G3_;
        float* ssc   = sgh + NB_*G3_;
        float* saux  = ssc + NB_*SP_;

        for (int i=tid;i<NB_*H_;i+=NT_){ sh1[i]=0.f; sh2[i]=0.f; }
        if (tid < NB_){
            int p = sol1[(size_t)(bb+tid)*S_];
            const float* xp = inst + ((size_t)(bb+tid)*S_+p)*2;
            saux[2*tid] = xp[0]; saux[2*tid+1] = xp[1];
        }
        __syncthreads();
        for (int i=tid;i<NB_*H_;i+=NT_){
            int b=i>>7, h=i&127;
            srh[i] = emb2(saux[2*b], saux[2*b+1], erW[2*h], erW[2*h+1], erb[h]);
        }
        __syncthreads();
        for (int t=1; t<S_; t++){
            gemv3_gates<H_>(gWih,gWhh,gbih,gbhh, srh, sh1, sgx, sgh, tid);
            __syncthreads();
            gru_update(sgx,sgh,sh1,tid);
            __syncthreads();
            proj_bcast(attnW + H_*H_, sh1, shp, tid);
            __syncthreads();
            attn_scores_ctx(shp, attnV, ssc, sctx, bb, tid);
            if (tid < NB_){
                int p = sol1[(size_t)(bb+tid)*S_ + t];
                const float* xp = inst + ((size_t)(bb+tid)*S_+p)*2;
                saux[2*tid] = xp[0]; saux[2*tid+1] = xp[1];
            }
            __syncthreads();
            for (int i=tid;i<NB_*H_;i+=NT_){
                int b=i>>7, h=i&127;
                float rv = emb2(saux[2*b], saux[2*b+1], erW[2*h], erW[2*h+1], erb[h]);
                srh[i] = rv;
                sfcin[b*256 + h]      = rv;
                sfcin[b*256 + H_ + h] = sctx[i];
            }
            __syncthreads();
            gemv3_gates<2*H_>(dWih,dWhh,dbih,dbhh, sfcin, sh2, sgx, sgh, tid);
            __syncthreads();
            gru_update(sgx,sgh,sh2,tid);
            __syncthreads();
        }
        for (int j=tid; j<SSZ_; j+=NT_){
            float am[NB_], al[NB_];
            #pragma unroll
            for (int b=0;b<NB_;b++){ am[b]=0.f; al[b]=0.f; }
            const float4* w1 = (const float4*)(e1W + (size_t)j*H_);
            const float4* w2 = (const float4*)(e2W + (size_t)j*H_);
            for (int kk=0;kk<H_/4;kk++){
                float4 a = w1[kk], c = w2[kk];
                #pragma unroll
                for (int b=0;b<NB_;b++){
                    float4 hv = *(const float4*)(sh2 + b*H_ + (kk<<2));
                    am[b]=__fmaf_rn(a.x,hv.x,am[b]); am[b]=__fmaf_rn(a.y,hv.y,am[b]);
                    am[b]=__fmaf_rn(a.z,hv.z,am[b]); am[b]=__fmaf_rn(a.w,hv.w,am[b]);
                    al[b]=__fmaf_rn(c.x,hv.x,al[b]); al[b]=__fmaf_rn(c.y,hv.y,al[b]);
                    al[b]=__fmaf_rn(c.z,hv.z,al[b]); al[b]=__fmaf_rn(c.w,hv.w,al[b]);
                }
            }
            #pragma unroll
            for (int b=0;b<NB_;b++){
                float mu=__fadd_rn(am[b], e1b[j]);
                float lv=__fadd_rn(al[b], e2b[j]);
                float ex = expf(__fmul_rn(0.5f, lv));
                float z  = __fadd_rn(mu, __fmul_rn(eps[(size_t)(bb+b)*SSZ_+j], ex));
                out_mu[(size_t)(bb+b)*SSZ_+j]=mu;
                out_lv[(size_t)(bb+b)*SSZ_+j]=lv;
                out_z [(size_t)(bb+b)*SSZ_+j]=z;
            }
        }
        __syncthreads();
    }

    // ======== DECODER (pair state) ========
    double* d_ssc = pool;                         // NB*SP doubles
    float* fb   = (float*)(d_ssc + NB_*SP_);
    float* h1h  = fb;            float* h1l  = h1h  + NB_*H_;
    float* rhh  = h1l  + NB_*H_; float* rhl  = rhh  + NB_*H_;
    float* hph  = rhl  + NB_*H_; float* hpl  = hph  + NB_*H_;
    float* ctxh = hpl  + NB_*H_; float* ctxl = ctxh + NB_*H_;
    float* foh  = ctxl + NB_*H_; float* fol  = foh  + NB_*H_;
    float* f1h  = fol  + NB_*H_; float* f1l  = f1h  + NB_*256;
    float* gxh  = f1l  + NB_*256;float* gxl  = gxh  + NB_*G3_;
    float* ghh  = gxl  + NB_*G3_;float* ghl  = ghh  + NB_*G3_;
    float* fzh  = ghl  + NB_*G3_;float* fzl  = fzh  + NB_*256;
    float* sscf = fzl  + NB_*256;
    float* smask= sscf + NB_*SP_;
    float* sZ   = smask+ NB_*SP_;
    float* saux = sZ   + NB_*SSZ_;

    __syncthreads();
    for (int i=tid;i<NB_*SSZ_;i+=NT_){
        int b=i/SSZ_, j=i-b*SSZ_;
        sZ[i] = out_z[(size_t)(bb+b)*SSZ_+j];
    }
    for (int i=tid;i<NB_*H_;i+=NT_){ h1h[i]=0.f; h1l[i]=0.f; }
    for (int i=tid;i<NB_*S_;i+=NT_){ int b=i/S_, s=i-b*S_; smask[b*SP_+s]=1.f; }
    __syncthreads();
    if (tid < NB_){
        int p0 = sol2[(size_t)(bb+tid)*S_];
        smask[tid*SP_+p0] = 0.f;
        out_idx[(size_t)(bb+tid)*S_] = (float)p0;
    }
    __syncthreads();
    {   // hoist fc1's Z slice
        int j = tid;
        if (j < 256){
            float s[NB_], c[NB_];
            #pragma unroll
            for (int b=0;b<NB_;b++){ s[b]=0.f; c[b]=0.f; }
            const float* wr = p1W + (size_t)j*FCK_ + H_;
            for (int k=0;k<SSZ_;k++){
                float w = wr[k];
                #pragma unroll
                for (int b=0;b<NB_;b++) dot2z(w, sZ[b*SSZ_+k], s[b], c[b]);
            }
            #pragma unroll
            for (int b=0;b<NB_;b++)
                dsplit((double)s[b]+(double)c[b], fzh[b*256+j], fzl[b*256+j]);
        }
    }
    __syncthreads();

    for (int t=1; t<S_; t++){
        if (tid < NB_){
            int p = sol2[(size_t)(bb+tid)*S_ + (t-1)];
            const float* xp = inst + ((size_t)(bb+tid)*S_+p)*2;
            saux[2*tid] = xp[0]; saux[2*tid+1] = xp[1];
        }
        __syncthreads();
        for (int i=tid;i<NB_*H_;i+=NT_){
            int b=i>>7, h=i&127;
            double d = fma((double)saux[2*b+1], (double)erW[2*h+1],
                           (double)saux[2*b]*(double)erW[2*h]) + (double)erb[h];
            dsplit(d, rhh[i], rhl[i]);
        }
        __syncthreads();
        gemvp(gWih, rhh, rhl, gbih, gxh, gxl, tid);
        gemvp(gWhh, h1h, h1l, gbhh, ghh, ghl, tid);
        __syncthreads();
        grup(gxh, gxl, ghh, ghl, h1h, h1l, tid);
        __syncthreads();
        projp(attnW + H_*H_, h1h, h1l, hph, hpl, tid);
        __syncthreads();
        attnp(hph, hpl, attnV, d_ssc, ctxh, ctxl, bb, tid);
        __syncthreads();
        {   // fc1
            int j = tid;
            if (j < 256){
                float s[NB_], c[NB_];
                #pragma unroll
                for (int b=0;b<NB_;b++){ s[b]=0.f; c[b]=0.f; }
                const float* wr = p1W + (size_t)j*FCK_;
                for (int k=0;k<H_;k++){
                    float w = wr[k];
                    #pragma unroll
                    for (int b=0;b<NB_;b++) dot2(w, ctxh[b*H_+k], ctxl[b*H_+k], s[b], c[b]);
                }
                const float* wr2 = wr + 228;
                for (int k=0;k<H_;k++){
                    float w = wr2[k];
                    #pragma unroll
                    for (int b=0;b<NB_;b++) dot2(w, rhh[b*H_+k], rhl[b*H_+k], s[b], c[b]);
                }
                double bj = (double)p1b[j];
                #pragma unroll
                for (int b=0;b<NB_;b++){
                    double v = (double)s[b] + (double)c[b]
                             + (double)fzh[b*256+j] + (double)fzl[b*256+j] + bj;
                    dsplit(v, f1h[b*256+j], f1l[b*256+j]);
                }
            }
        }
        __syncthreads();
        {   // fc2 (2 b per thread-group)
            int h = tid & 127, gsel = tid >> 7;
            float s[2], c[2];
            #pragma unroll
            for (int i=0;i<2;i++){ s[i]=0.f; c[i]=0.f; }
            const float* wr = p2W + (size_t)h*256;
            for (int k=0;k<256;k++){
                float w = wr[k];
                #pragma unroll
                for (int i=0;i<2;i++)
                    dot2(w, f1h[(gsel*2+i)*256+k], f1l[(gsel*2+i)*256+k], s[i], c[i]);
            }
            double bh = (double)p2b[h];
            #pragma unroll
            for (int i=0;i<2;i++)
                dsplit((double)s[i]+(double)c[i]+bh,
                       foh[(gsel*2+i)*H_+h], fol[(gsel*2+i)*H_+h]);
        }
        __syncthreads();
        projp(ptrW + H_*H_, foh, fol, hph, hpl, tid);
        __syncthreads();
        // ---- pointer select ----
        {
            int lane = tid & 31, b = tid >> 5;
            if (b < NB_){
                const float* ipA = g_ipt + (size_t)(bb+b)*S_*H_;
                float fp0=hph[b*H_+lane], fp1=hph[b*H_+lane+32],
                      fp2=hph[b*H_+lane+64], fp3=hph[b*H_+lane+96];
                float v0=ptrV[lane], v1=ptrV[lane+32], v2=ptrV[lane+64], v3=ptrV[lane+96];
                for (int s0=0; s0<S_; s0+=4){
                    float acc[4];
                    #pragma unroll
                    for (int u=0;u<4;u++){
                        const float* q = ipA + (s0+u)*H_;
                        float a = __fmul_rn(xla_tanh(__fadd_rn(q[lane],    fp0)), v0);
                        a = __fmaf_rn(xla_tanh(__fadd_rn(q[lane+32], fp1)), v1, a);
                        a = __fmaf_rn(xla_tanh(__fadd_rn(q[lane+64], fp2)), v2, a);
                        a = __fmaf_rn(xla_tanh(__fadd_rn(q[lane+96], fp3)), v3, a);
                        acc[u]=a;
                    }
                    #pragma unroll
                    for (int off=16; off; off>>=1){
                        #pragma unroll
                        for (int u=0;u<4;u++)
                            acc[u] = __fadd_rn(acc[u], __shfl_xor_sync(0xffffffffu, acc[u], off));
                    }
                    if (lane < 4){
                        float msk = smask[b*SP_ + s0 + lane];
                        sscf[b*SP_ + s0 + lane] = (msk > 0.5f) ? acc[lane] : NEG_INF;
                    }
                }
                __syncwarp();
                float m1 = NEG_INF;
                for (int s=lane; s<S_; s+=32) m1 = fmaxf(m1, sscf[b*SP_+s]);
                m1 = wmax(m1);
                float thr = m1 - NEARTOP_;
                const float* ipDh = g_ipth + (size_t)(bb+b)*S_*H_;
                const float* ipDl = g_iptl + (size_t)(bb+b)*S_*H_;
                double hp0=(double)hph[b*H_+lane]   +(double)hpl[b*H_+lane];
                double hq1=(double)hph[b*H_+lane+32]+(double)hpl[b*H_+lane+32];
                double hq2=(double)hph[b*H_+lane+64]+(double)hpl[b*H_+lane+64];
                double hq3=(double)hph[b*H_+lane+96]+(double)hpl[b*H_+lane+96];
                double dv0=(double)v0, dv1=(double)v1, dv2=(double)v2, dv3=(double)v3;
                for (int s=0; s<S_; s++){
                    bool live = smask[b*SP_+s] > 0.5f;
                    if (live && sscf[b*SP_+s] >= thr){
                        double q0=(double)ipDh[s*H_+lane]   +(double)ipDl[s*H_+lane];
                        double q1=(double)ipDh[s*H_+lane+32]+(double)ipDl[s*H_+lane+32];
                        double q2=(double)ipDh[s*H_+lane+64]+(double)ipDl[s*H_+lane+64];
                        double q3=(double)ipDh[s*H_+lane+96]+(double)ipDl[s*H_+lane+96];
                        double a = tanh64p(q0+hp0)*dv0;
                        a = fma(tanh64p(q1+hq1), dv1, a);
                        a = fma(tanh64p(q2+hq2), dv2, a);
                        a = fma(tanh64p(q3+hq3), dv3, a);
                        a = wsum64(a);
                        if (lane==0) d_ssc[b*SP_+s] = a;
                    } else {
                        if (lane==0) d_ssc[b*SP_+s] = live ? (double)sscf[b*SP_+s] : -1e300;
                    }
                }
                __syncwarp();
                double m = -1e300;
                for (int s=lane; s<S_; s+=32) m = fmax(m, d_ssc[b*SP_+s]);
                m = wmax64(m);
                double sum = 0.0;
                for (int s=lane; s<S_; s+=32) sum += exp(d_ssc[b*SP_+s]-m);
                sum = wsum64(sum);
                __syncwarp();
                float me = -1.0f; int mi = S_;
                for (int s=lane; s<S_; s+=32){
                    float p32 = (float)(exp(d_ssc[b*SP_+s]-m)/sum);
                    sscf[b*SP_+s] = p32;
                    if (p32 > me){ me = p32; mi = s; }
                }
                #pragma unroll
                for (int off=16; off; off>>=1){
                    float om = __shfl_xor_sync(0xffffffffu, me, off);
                    int   oi = __shfl_xor_sync(0xffffffffu, mi, off);
                    if (om > me || (om == me && oi < mi)){ me = om; mi = oi; }
                }
                __syncwarp();
                int tgt = sol2[(size_t)(bb+b)*S_ + t];
                if (lane == 0){
                    out_lp[(size_t)(bb+b)*(S_-1) + (t-1)] = logf(sscf[b*SP_+tgt]);
                    out_idx[(size_t)(bb+b)*S_ + t] = (float)mi;
                    smask[b*SP_+tgt] = 0.f;
                }
            }
        }
        __syncthreads();
    }
}

extern "C" void kernel_launch(void* const* d_in, const int* in_sizes, int n_in,
                              void* d_out, int out_size) {
    const float* inst = (const float*)d_in[0];
    const int*   sol1 = (const int*)  d_in[1];
    const int*   sol2 = (const int*)  d_in[2];
    const float* eps  = (const float*)d_in[3];
    const float* eiW  = (const float*)d_in[4];
    const float* eib  = (const float*)d_in[5];
    const float* erW  = (const float*)d_in[6];
    const float* erb  = (const float*)d_in[7];
    const float* attnW= (const float*)d_in[8];
    const float* attnV= (const float*)d_in[9];
    const float* gWih = (const float*)d_in[10];
    const float* gWhh = (const float*)d_in[11];
    const float* gbih = (const float*)d_in[12];
    const float* gbhh = (const float*)d_in[13];
    const float* dWih = (const float*)d_in[14];
    const float* dWhh = (const float*)d_in[15];
    const float* dbih = (const float*)d_in[16];
    const float* dbhh = (const float*)d_in[17];
    const float* e1W  = (const float*)d_in[18];
    const float* e1b  = (const float*)d_in[19];
    const float* e2W  = (const float*)d_in[20];
    const float* e2b  = (const float*)d_in[21];
    const float* ptrW = (const float*)d_in[22];
    const float* ptrV = (const float*)d_in[23];
    const float* p1W  = (const float*)d_in[24];
    const float* p1b  = (const float*)d_in[25];
    const float* p2W  = (const float*)d_in[26];
    const float* p2b  = (const float*)d_in[27];
    float* out = (float*)d_out;

    size_t dbl = (size_t)(NB_*SP_);
    size_t flt = (size_t)(10*NB_*H_ + 2*NB_*256 + 4*NB_*G3_ + 2*NB_*256
                        + 2*NB_*SP_ + NB_*SSZ_ + 2*NB_ + 64);
    size_t smem_dec = dbl*sizeof(double) + flt*sizeof(float);
    size_t smem_enc = (size_t)(5*NB_*H_ + NB_*256 + 2*NB_*G3_ + NB_*SP_ + 2*NB_ + 64)*sizeof(float);
    size_t smem = smem_dec > smem_enc ? smem_dec : smem_enc;
    cudaFuncSetAttribute(vae_main, cudaFuncAttributeMaxDynamicSharedMemorySize, (int)smem);

    dim3 gpre(B_, S_/STILE_);
    precompute_kernel<<<gpre, 256>>>(inst, eiW, eib, attnW, ptrW);
    precompute_pair_kernel<<<gpre, 256>>>(attnW, ptrW);
    vae_main<<<B_/NB_, NT_, smem>>>(inst, sol1, sol2, eps, erW, erb, attnW, attnV,
                                    gWih, gWhh, gbih, gbhh, dWih, dWhh, dbih, dbhh,
                                    e1W, e1b, e2W, e2b, ptrW, ptrV,
                                    p1W, p1b, p2W, p2b, out);
}